// round 1
// baseline (speedup 1.0000x reference)
#include <cuda_runtime.h>
#include <cuda_bf16.h>
#include <math.h>

// Problem constants
#define BB 32
#define TT 256
#define DD 2048
#define HH 16
#define DKK 64
// rows = B*T = 8192, proj width = 2048 (k:0..1023, v:1024..2047)

__device__ float g_proj[8192 * 2048];   // k|v projections, row-major (B*T, 2048)
__device__ float g_bg[8192 * 32];       // beta logits (0..15), gamma logits (16..31)

// ---------------------------------------------------------------------------
// Kernel 1: C = content @ [k_w; v_w]^T   (M=8192, K=2048, N=2048)
// 128x128 block tile, BK=16, 256 threads, 8x8 per-thread microtile.
// ---------------------------------------------------------------------------
#define GBM 128
#define GBN 128
#define GBK 16

__global__ __launch_bounds__(256, 2)
void sgemm_kv(const float* __restrict__ A,
              const float* __restrict__ Wk,
              const float* __restrict__ Wv)
{
    __shared__ float As[GBK][GBM];
    __shared__ float Bs[GBK][GBN];

    const int nt = blockIdx.x;              // 0..15
    const int m0 = blockIdx.y * GBM;
    const int nb = nt * GBN;                // output column base
    const float* Wp = (nt < 8) ? Wk : Wv;
    const int ncol0 = (nt < 8) ? nt * GBN : (nt - 8) * GBN;

    const int tid = threadIdx.x;
    const int a_row = tid >> 1;             // 0..127
    const int a_col = (tid & 1) << 3;       // 0 or 8
    const int tr = tid >> 4;                // 0..15
    const int tc = tid & 15;                // 0..15

    float acc[8][8];
#pragma unroll
    for (int i = 0; i < 8; i++)
#pragma unroll
        for (int j = 0; j < 8; j++) acc[i][j] = 0.f;

    for (int k0 = 0; k0 < DD; k0 += GBK) {
        // load global -> regs
        const float4* ap = reinterpret_cast<const float4*>(
            &A[(size_t)(m0 + a_row) * DD + k0 + a_col]);
        float4 p0 = ap[0], p1 = ap[1];
        const float4* bp = reinterpret_cast<const float4*>(
            &Wp[(size_t)(ncol0 + a_row) * DD + k0 + a_col]);
        float4 q0 = bp[0], q1 = bp[1];

        __syncthreads();
        As[a_col + 0][a_row] = p0.x; As[a_col + 1][a_row] = p0.y;
        As[a_col + 2][a_row] = p0.z; As[a_col + 3][a_row] = p0.w;
        As[a_col + 4][a_row] = p1.x; As[a_col + 5][a_row] = p1.y;
        As[a_col + 6][a_row] = p1.z; As[a_col + 7][a_row] = p1.w;
        Bs[a_col + 0][a_row] = q0.x; Bs[a_col + 1][a_row] = q0.y;
        Bs[a_col + 2][a_row] = q0.z; Bs[a_col + 3][a_row] = q0.w;
        Bs[a_col + 4][a_row] = q1.x; Bs[a_col + 5][a_row] = q1.y;
        Bs[a_col + 6][a_row] = q1.z; Bs[a_col + 7][a_row] = q1.w;
        __syncthreads();

#pragma unroll
        for (int kk = 0; kk < GBK; kk++) {
            float4 a0 = *reinterpret_cast<const float4*>(&As[kk][tr * 8]);
            float4 a1 = *reinterpret_cast<const float4*>(&As[kk][tr * 8 + 4]);
            float4 b0 = *reinterpret_cast<const float4*>(&Bs[kk][tc * 8]);
            float4 b1 = *reinterpret_cast<const float4*>(&Bs[kk][tc * 8 + 4]);
            float av[8] = {a0.x, a0.y, a0.z, a0.w, a1.x, a1.y, a1.z, a1.w};
            float bv[8] = {b0.x, b0.y, b0.z, b0.w, b1.x, b1.y, b1.z, b1.w};
#pragma unroll
            for (int i = 0; i < 8; i++)
#pragma unroll
                for (int j = 0; j < 8; j++)
                    acc[i][j] = fmaf(av[i], bv[j], acc[i][j]);
        }
    }

#pragma unroll
    for (int i = 0; i < 8; i++) {
        float* crow = &g_proj[(size_t)(m0 + tr * 8 + i) * DD + nb + tc * 8];
        float4 o0 = make_float4(acc[i][0], acc[i][1], acc[i][2], acc[i][3]);
        float4 o1 = make_float4(acc[i][4], acc[i][5], acc[i][6], acc[i][7]);
        reinterpret_cast<float4*>(crow)[0] = o0;
        reinterpret_cast<float4*>(crow)[1] = o1;
    }
}

// ---------------------------------------------------------------------------
// Kernel 2: beta/gamma logits. 8 rows per block, 32 outputs, 256 threads.
// ---------------------------------------------------------------------------
__global__ __launch_bounds__(256)
void proj_bg(const float* __restrict__ A,
             const float* __restrict__ b_w,
             const float* __restrict__ ts_w,
             const float* __restrict__ b_b,
             const float* __restrict__ ts_b)
{
    __shared__ float As[8][256];
    __shared__ float Ws[32][257];

    const int rb = blockIdx.x * 8;
    const int tid = threadIdx.x;
    const int r = tid >> 5;     // 0..7
    const int j = tid & 31;     // 0..31
    float acc = 0.f;

    for (int k0 = 0; k0 < DD; k0 += 256) {
        __syncthreads();
        for (int i = tid; i < 8 * 256; i += 256) {
            int row = i >> 8, col = i & 255;
            As[row][col] = A[(size_t)(rb + row) * DD + k0 + col];
        }
        for (int i = tid; i < 32 * 256; i += 256) {
            int wr = i >> 8, wc = i & 255;
            float val = (wr < 16) ? b_w[(size_t)wr * DD + k0 + wc]
                                  : ts_w[(size_t)(wr - 16) * DD + k0 + wc];
            Ws[wr][wc] = val;
        }
        __syncthreads();
#pragma unroll 8
        for (int d = 0; d < 256; d++)
            acc = fmaf(As[r][d], Ws[j][d], acc);
    }

    float bias = (j < 16) ? b_b[j] : ts_b[j - 16];
    g_bg[(size_t)(rb + r) * 32 + j] = acc + bias;
}

// ---------------------------------------------------------------------------
// Kernel 3: per-(b,h) gated delta-rule recurrence.
// 64 threads; thread v owns W[v][0..63] in registers.
// ---------------------------------------------------------------------------
#define CH 32  // time-chunk staged in shared

__global__ __launch_bounds__(64)
void recurrent_update(const float* __restrict__ W_old,
                      const float* __restrict__ hd,
                      float* __restrict__ out)
{
    const int bh = blockIdx.x;
    const int b = bh >> 4;
    const int h = bh & 15;
    const int v = threadIdx.x;

    __shared__ float ks[CH][DKK];
    __shared__ float vs[CH][DKK];
    __shared__ float betas[CH], gammas[CH], ninv[CH];

    float W[DKK];
    const float* wrow = W_old + ((size_t)bh * DKK + v) * DKK;
#pragma unroll
    for (int d = 0; d < DKK; d += 4) {
        float4 t = *reinterpret_cast<const float4*>(&wrow[d]);
        W[d] = t.x; W[d+1] = t.y; W[d+2] = t.z; W[d+3] = t.w;
    }
    const float hdl = hd[h];

    for (int t0 = 0; t0 < TT; t0 += CH) {
        __syncthreads();
        // stage k and v chunks (coalesced: d = threadIdx.x)
        for (int i = v; i < CH * DKK; i += DKK) {
            int s = i >> 6, d = i & 63;
            size_t row = (size_t)(b * TT + t0 + s) * DD;
            ks[s][d] = g_proj[row + h * DKK + d];
            vs[s][d] = g_proj[row + 1024 + h * DKK + d];
        }
        __syncthreads();
        if (v < CH) {
            int s = v;
            float nsq = 0.f;
#pragma unroll
            for (int d = 0; d < DKK; d++) { float x = ks[s][d]; nsq = fmaf(x, x, nsq); }
            ninv[s] = rsqrtf(fmaxf(nsq, 1e-24f));
            size_t brow = (size_t)(b * TT + t0 + s) * 32;
            float bl = g_bg[brow + h];
            betas[s] = 1.f / (1.f + expf(-bl));
            float gl = g_bg[brow + 16 + h] + hdl;
            gammas[s] = 1.f / (1.f + expf(-gl));
        }
        __syncthreads();
        for (int i = v; i < CH * DKK; i += DKK) {
            int s = i >> 6, d = i & 63;
            ks[s][d] *= ninv[s];
        }
        __syncthreads();

        for (int s = 0; s < CH; s++) {
            float a0 = 0.f, a1 = 0.f, a2 = 0.f, a3 = 0.f;
#pragma unroll
            for (int d = 0; d < DKK; d += 4) {
                a0 = fmaf(W[d],     ks[s][d],     a0);
                a1 = fmaf(W[d + 1], ks[s][d + 1], a1);
                a2 = fmaf(W[d + 2], ks[s][d + 2], a2);
                a3 = fmaf(W[d + 3], ks[s][d + 3], a3);
            }
            float y = (a0 + a1) + (a2 + a3);
            float c = betas[s] * (vs[s][v] - y);
            float g = gammas[s];
#pragma unroll
            for (int d = 0; d < DKK; d++)
                W[d] = fmaf(c, ks[s][d], g * W[d]);
        }
    }

    float* orow = out + ((size_t)bh * DKK + v) * DKK;
#pragma unroll
    for (int d = 0; d < DKK; d += 4) {
        float4 t = make_float4(W[d], W[d+1], W[d+2], W[d+3]);
        *reinterpret_cast<float4*>(&orow[d]) = t;
    }
}

// ---------------------------------------------------------------------------
extern "C" void kernel_launch(void* const* d_in, const int* in_sizes, int n_in,
                              void* d_out, int out_size)
{
    const float* W_old   = (const float*)d_in[0];
    const float* content = (const float*)d_in[1];
    const float* k_w     = (const float*)d_in[2];
    const float* v_w     = (const float*)d_in[3];
    const float* b_w     = (const float*)d_in[4];
    const float* b_b     = (const float*)d_in[5];
    const float* ts_w    = (const float*)d_in[6];
    const float* ts_b    = (const float*)d_in[7];
    const float* hd      = (const float*)d_in[8];
    float* out = (float*)d_out;

    dim3 g1(16, 64);
    sgemm_kv<<<g1, 256>>>(content, k_w, v_w);
    proj_bg<<<1024, 256>>>(content, b_w, ts_w, b_b, ts_b);
    recurrent_update<<<BB * HH, 64>>>(W_old, hd, out);
}

// round 3
// speedup vs baseline: 2.1291x; 2.1291x over previous
#include <cuda_runtime.h>
#include <cuda_bf16.h>
#include <math.h>
#include <stdint.h>

// Problem constants
#define BB 32
#define TT 256
#define DD 2048
#define HH 16
#define DKK 64

__device__ float g_proj[8192 * 2048];   // k|v projections, row-major (B*T, 2048)
__device__ float g_bg[8192 * 32];       // beta logits (0..15), gamma logits (16..31)

// ---------------------------------------------------------------------------
// GEMM kernel 1: C[8192,2048] = content @ [k_w; v_w]^T  via mma.sync bf16
// split-precision (hi/lo), CTA tile 128x128, K-step 16, 8 warps (4x2).
// ---------------------------------------------------------------------------
#define TM 128
#define TN 128
#define TK 16
#define NC (DD / TK)        // 128 chunks
#define PITCH 48            // bytes per 16-element bf16 row (conflict-free ldmatrix)
#define PLANE 6144          // 128 rows * 48B
#define STAGE (4 * PLANE)   // Ahi, Alo, Bhi, Blo
#define SMEMG (2 * STAGE)   // 49152 double-buffered

__device__ __forceinline__ uint32_t smem_u32(const void* p) {
    uint32_t a;
    asm("{ .reg .u64 t; cvta.to.shared.u64 t, %1; cvt.u32.u64 %0, t; }" : "=r"(a) : "l"(p));
    return a;
}

__device__ __forceinline__ void cvt_split(float4 x, uint2& hv, uint2& lv) {
    uint32_t h0 = __float_as_uint(x.x) & 0xFFFF0000u;
    uint32_t h1 = __float_as_uint(x.y) & 0xFFFF0000u;
    uint32_t h2 = __float_as_uint(x.z) & 0xFFFF0000u;
    uint32_t h3 = __float_as_uint(x.w) & 0xFFFF0000u;
    float l0 = x.x - __uint_as_float(h0), l1 = x.y - __uint_as_float(h1);
    float l2 = x.z - __uint_as_float(h2), l3 = x.w - __uint_as_float(h3);
    hv.x = (h0 >> 16) | h1;
    hv.y = (h2 >> 16) | h3;
    asm("cvt.rn.bf16x2.f32 %0, %2, %1;" : "=r"(lv.x) : "f"(l0), "f"(l1));
    asm("cvt.rn.bf16x2.f32 %0, %2, %1;" : "=r"(lv.y) : "f"(l2), "f"(l3));
}

__device__ __forceinline__ void ldmx4(uint32_t* r, uint32_t addr) {
    asm volatile("ldmatrix.sync.aligned.m8n8.x4.shared.b16 {%0,%1,%2,%3}, [%4];"
                 : "=r"(r[0]), "=r"(r[1]), "=r"(r[2]), "=r"(r[3]) : "r"(addr));
}

__device__ __forceinline__ void mma16816(float* d, const uint32_t* a,
                                         uint32_t b0, uint32_t b1) {
    asm volatile(
        "mma.sync.aligned.m16n8k16.row.col.f32.bf16.bf16.f32 "
        "{%0,%1,%2,%3}, {%4,%5,%6,%7}, {%8,%9}, {%0,%1,%2,%3};"
        : "+f"(d[0]), "+f"(d[1]), "+f"(d[2]), "+f"(d[3])
        : "r"(a[0]), "r"(a[1]), "r"(a[2]), "r"(a[3]), "r"(b0), "r"(b1));
}

__global__ __launch_bounds__(256)
void gemm_kv_mma(const float* __restrict__ A,
                 const float* __restrict__ Wk,
                 const float* __restrict__ Wv)
{
    extern __shared__ char sm[];
    const uint32_t sb = smem_u32(sm);
    const int tid = threadIdx.x;
    const int wid = tid >> 5;
    const int lane = tid & 31;
    const int wm = wid >> 1;           // 0..3
    const int wn = wid & 1;            // 0..1

    const int m0 = blockIdx.y * TM;
    const int n0 = blockIdx.x * TN;
    const float* Bg = (n0 < 1024) ? (Wk + (size_t)n0 * DD)
                                  : (Wv + (size_t)(n0 - 1024) * DD);

    // staging: each thread loads 2 float4 of A + 2 of B per chunk
    const int srow0 = tid >> 2;            // 0..63
    const int srow1 = srow0 + 64;          // 64..127
    const int sc4 = tid & 3;               // 0..3 (which float4 within 16 k)
    const float* Ap0 = A + (size_t)(m0 + srow0) * DD + sc4 * 4;
    const float* Ap1 = A + (size_t)(m0 + srow1) * DD + sc4 * 4;
    const float* Bp0 = Bg + (size_t)srow0 * DD + sc4 * 4;
    const float* Bp1 = Bg + (size_t)srow1 * DD + sc4 * 4;
    const uint32_t soff0 = srow0 * PITCH + sc4 * 8;
    const uint32_t soff1 = srow1 * PITCH + sc4 * 8;

    float acc[2][8][4];
#pragma unroll
    for (int i = 0; i < 2; i++)
#pragma unroll
        for (int j = 0; j < 8; j++)
#pragma unroll
            for (int q = 0; q < 4; q++) acc[i][j][q] = 0.f;

    // ldmatrix fragment addresses (offsets within a stage)
    const uint32_t a_frag_off =
        (uint32_t)((wm * 32 + (lane & 7) + ((lane & 8) ? 8 : 0)) * PITCH +
                   ((lane & 16) ? 16 : 0));
    const uint32_t b_frag_off =
        (uint32_t)((wn * 64 + (lane & 7) + ((lane & 16) ? 8 : 0)) * PITCH +
                   ((lane & 8) ? 16 : 0));

    uint2 ahv0, alv0, ahv1, alv1, bhv0, blv0, bhv1, blv1;
    {   // prefetch chunk 0
        float4 x0 = *reinterpret_cast<const float4*>(Ap0);
        float4 x1 = *reinterpret_cast<const float4*>(Ap1);
        float4 y0 = *reinterpret_cast<const float4*>(Bp0);
        float4 y1 = *reinterpret_cast<const float4*>(Bp1);
        cvt_split(x0, ahv0, alv0); cvt_split(x1, ahv1, alv1);
        cvt_split(y0, bhv0, blv0); cvt_split(y1, bhv1, blv1);
    }

    for (int c = 0; c < NC; c++) {
        char* stg = sm + (c & 1) * STAGE;
        // store staged chunk c
        *reinterpret_cast<uint2*>(stg + soff0) = ahv0;
        *reinterpret_cast<uint2*>(stg + soff1) = ahv1;
        *reinterpret_cast<uint2*>(stg + PLANE + soff0) = alv0;
        *reinterpret_cast<uint2*>(stg + PLANE + soff1) = alv1;
        *reinterpret_cast<uint2*>(stg + 2 * PLANE + soff0) = bhv0;
        *reinterpret_cast<uint2*>(stg + 2 * PLANE + soff1) = bhv1;
        *reinterpret_cast<uint2*>(stg + 3 * PLANE + soff0) = blv0;
        *reinterpret_cast<uint2*>(stg + 3 * PLANE + soff1) = blv1;
        __syncthreads();

        // prefetch chunk c+1 (LDG latency overlapped with mma below)
        if (c + 1 < NC) {
            const size_t ko = (size_t)(c + 1) * TK;
            float4 x0 = *reinterpret_cast<const float4*>(Ap0 + ko);
            float4 x1 = *reinterpret_cast<const float4*>(Ap1 + ko);
            float4 y0 = *reinterpret_cast<const float4*>(Bp0 + ko);
            float4 y1 = *reinterpret_cast<const float4*>(Bp1 + ko);
            cvt_split(x0, ahv0, alv0); cvt_split(x1, ahv1, alv1);
            cvt_split(y0, bhv0, blv0); cvt_split(y1, bhv1, blv1);
        }

        // fragments for chunk c
        const uint32_t stgb = sb + (c & 1) * STAGE;
        uint32_t Ahi[2][4], Alo[2][4];
#pragma unroll
        for (int mt = 0; mt < 2; mt++) {
            ldmx4(Ahi[mt], stgb + a_frag_off + mt * 16 * PITCH);
            ldmx4(Alo[mt], stgb + PLANE + a_frag_off + mt * 16 * PITCH);
        }
        uint32_t Bhi[4][4], Blo[4][4];
#pragma unroll
        for (int np = 0; np < 4; np++) {
            ldmx4(Bhi[np], stgb + 2 * PLANE + b_frag_off + np * 16 * PITCH);
            ldmx4(Blo[np], stgb + 3 * PLANE + b_frag_off + np * 16 * PITCH);
        }

#pragma unroll
        for (int mt = 0; mt < 2; mt++)
#pragma unroll
            for (int np = 0; np < 4; np++) {
                mma16816(acc[mt][2 * np],     Ahi[mt], Bhi[np][0], Bhi[np][1]);
                mma16816(acc[mt][2 * np + 1], Ahi[mt], Bhi[np][2], Bhi[np][3]);
                mma16816(acc[mt][2 * np],     Ahi[mt], Blo[np][0], Blo[np][1]);
                mma16816(acc[mt][2 * np + 1], Ahi[mt], Blo[np][2], Blo[np][3]);
                mma16816(acc[mt][2 * np],     Alo[mt], Bhi[np][0], Bhi[np][1]);
                mma16816(acc[mt][2 * np + 1], Alo[mt], Bhi[np][2], Bhi[np][3]);
            }
    }

    // epilogue
#pragma unroll
    for (int mt = 0; mt < 2; mt++) {
        const int row = m0 + wm * 32 + mt * 16 + (lane >> 2);
#pragma unroll
        for (int nt = 0; nt < 8; nt++) {
            const int col = n0 + wn * 64 + nt * 8 + 2 * (lane & 3);
            float* p0 = g_proj + (size_t)row * DD + col;
            float* p1 = g_proj + (size_t)(row + 8) * DD + col;
            *reinterpret_cast<float2*>(p0) = make_float2(acc[mt][nt][0], acc[mt][nt][1]);
            *reinterpret_cast<float2*>(p1) = make_float2(acc[mt][nt][2], acc[mt][nt][3]);
        }
    }
}

// ---------------------------------------------------------------------------
// Kernel 2: beta/gamma logits. 8 rows per block, 32 outputs, 256 threads.
// ---------------------------------------------------------------------------
__global__ __launch_bounds__(256)
void proj_bg(const float* __restrict__ A,
             const float* __restrict__ b_w,
             const float* __restrict__ ts_w,
             const float* __restrict__ b_b,
             const float* __restrict__ ts_b)
{
    __shared__ float As[8][256];
    __shared__ float Ws[32][257];

    const int rb = blockIdx.x * 8;
    const int tid = threadIdx.x;
    const int r = tid >> 5;
    const int j = tid & 31;
    float acc = 0.f;

    for (int k0 = 0; k0 < DD; k0 += 256) {
        __syncthreads();
        for (int i = tid; i < 8 * 256; i += 256) {
            int row = i >> 8, col = i & 255;
            As[row][col] = A[(size_t)(rb + row) * DD + k0 + col];
        }
        for (int i = tid; i < 32 * 256; i += 256) {
            int wr = i >> 8, wc = i & 255;
            float val = (wr < 16) ? b_w[(size_t)wr * DD + k0 + wc]
                                  : ts_w[(size_t)(wr - 16) * DD + k0 + wc];
            Ws[wr][wc] = val;
        }
        __syncthreads();
#pragma unroll 8
        for (int d = 0; d < 256; d++)
            acc = fmaf(As[r][d], Ws[j][d], acc);
    }

    float bias = (j < 16) ? b_b[j] : ts_b[j - 16];
    g_bg[(size_t)(rb + r) * 32 + j] = acc + bias;
}

// ---------------------------------------------------------------------------
// Kernel 3: per-(b,h) gated delta-rule recurrence.
// ---------------------------------------------------------------------------
#define CH 32

__global__ __launch_bounds__(64)
void recurrent_update(const float* __restrict__ W_old,
                      const float* __restrict__ hd,
                      float* __restrict__ out)
{
    const int bh = blockIdx.x;
    const int b = bh >> 4;
    const int h = bh & 15;
    const int v = threadIdx.x;

    __shared__ float ks[CH][DKK];
    __shared__ float vs[CH][DKK];
    __shared__ float betas[CH], gammas[CH], ninv[CH];

    float W[DKK];
    const float* wrow = W_old + ((size_t)bh * DKK + v) * DKK;
#pragma unroll
    for (int d = 0; d < DKK; d += 4) {
        float4 t = *reinterpret_cast<const float4*>(&wrow[d]);
        W[d] = t.x; W[d+1] = t.y; W[d+2] = t.z; W[d+3] = t.w;
    }
    const float hdl = hd[h];

    for (int t0 = 0; t0 < TT; t0 += CH) {
        __syncthreads();
        for (int i = v; i < CH * DKK; i += DKK) {
            int s = i >> 6, d = i & 63;
            size_t row = (size_t)(b * TT + t0 + s) * DD;
            ks[s][d] = g_proj[row + h * DKK + d];
            vs[s][d] = g_proj[row + 1024 + h * DKK + d];
        }
        __syncthreads();
        if (v < CH) {
            int s = v;
            float nsq = 0.f;
#pragma unroll
            for (int d = 0; d < DKK; d++) { float x = ks[s][d]; nsq = fmaf(x, x, nsq); }
            ninv[s] = rsqrtf(fmaxf(nsq, 1e-24f));
            size_t brow = (size_t)(b * TT + t0 + s) * 32;
            float bl = g_bg[brow + h];
            betas[s] = 1.f / (1.f + expf(-bl));
            float gl = g_bg[brow + 16 + h] + hdl;
            gammas[s] = 1.f / (1.f + expf(-gl));
        }
        __syncthreads();
        for (int i = v; i < CH * DKK; i += DKK) {
            int s = i >> 6, d = i & 63;
            ks[s][d] *= ninv[s];
        }
        __syncthreads();

        for (int s = 0; s < CH; s++) {
            float a0 = 0.f, a1 = 0.f, a2 = 0.f, a3 = 0.f;
#pragma unroll
            for (int d = 0; d < DKK; d += 4) {
                a0 = fmaf(W[d],     ks[s][d],     a0);
                a1 = fmaf(W[d + 1], ks[s][d + 1], a1);
                a2 = fmaf(W[d + 2], ks[s][d + 2], a2);
                a3 = fmaf(W[d + 3], ks[s][d + 3], a3);
            }
            float y = (a0 + a1) + (a2 + a3);
            float c = betas[s] * (vs[s][v] - y);
            float g = gammas[s];
#pragma unroll
            for (int d = 0; d < DKK; d++)
                W[d] = fmaf(c, ks[s][d], g * W[d]);
        }
    }

    float* orow = out + ((size_t)bh * DKK + v) * DKK;
#pragma unroll
    for (int d = 0; d < DKK; d += 4) {
        float4 t = make_float4(W[d], W[d+1], W[d+2], W[d+3]);
        *reinterpret_cast<float4*>(&orow[d]) = t;
    }
}

// ---------------------------------------------------------------------------
extern "C" void kernel_launch(void* const* d_in, const int* in_sizes, int n_in,
                              void* d_out, int out_size)
{
    const float* W_old   = (const float*)d_in[0];
    const float* content = (const float*)d_in[1];
    const float* k_w     = (const float*)d_in[2];
    const float* v_w     = (const float*)d_in[3];
    const float* b_w     = (const float*)d_in[4];
    const float* b_b     = (const float*)d_in[5];
    const float* ts_w    = (const float*)d_in[6];
    const float* ts_b    = (const float*)d_in[7];
    const float* hd      = (const float*)d_in[8];
    float* out = (float*)d_out;

    cudaFuncSetAttribute(gemm_kv_mma, cudaFuncAttributeMaxDynamicSharedMemorySize,
                         SMEMG);

    dim3 g1(DD / TN, 8192 / TM);   // (16, 64)
    gemm_kv_mma<<<g1, 256, SMEMG>>>(content, k_w, v_w);
    proj_bg<<<1024, 256>>>(content, b_w, ts_w, b_b, ts_b);
    recurrent_update<<<BB * HH, 64>>>(W_old, hd, out);
}

// round 4
// speedup vs baseline: 2.1586x; 1.0138x over previous
#include <cuda_runtime.h>
#include <cuda_bf16.h>
#include <math.h>
#include <stdint.h>

// Problem constants
#define BB 32
#define TT 256
#define DD 2048
#define HH 16
#define DKK 64

__device__ float g_proj[8192 * 2048];   // k|v projections (B*T, 2048)
__device__ float g_bg[8192 * 32];       // beta logits (0..15), gamma logits (16..31)

// pre-split bf16 planes
__device__ __nv_bfloat16 g_Ahi[8192 * 2048];
__device__ __nv_bfloat16 g_Alo[8192 * 2048];
__device__ __nv_bfloat16 g_Bhi[2048 * 2048];   // rows 0..1023 = k_w, 1024..2047 = v_w
__device__ __nv_bfloat16 g_Blo[2048 * 2048];

__device__ __forceinline__ uint32_t smem_u32(const void* p) {
    uint32_t a;
    asm("{ .reg .u64 t; cvta.to.shared.u64 t, %1; cvt.u32.u64 %0, t; }" : "=r"(a) : "l"(p));
    return a;
}

// ---------------------------------------------------------------------------
// Kernel 0: split fp32 -> bf16 hi/lo planes
// ---------------------------------------------------------------------------
__global__ __launch_bounds__(256)
void cvt_split_kernel(const float4* __restrict__ src,
                      uint2* __restrict__ dhi, uint2* __restrict__ dlo, int n4)
{
    int i = blockIdx.x * blockDim.x + threadIdx.x;
    int stride = gridDim.x * blockDim.x;
    for (; i < n4; i += stride) {
        float4 x = src[i];
        uint32_t h0 = __float_as_uint(x.x) & 0xFFFF0000u;
        uint32_t h1 = __float_as_uint(x.y) & 0xFFFF0000u;
        uint32_t h2 = __float_as_uint(x.z) & 0xFFFF0000u;
        uint32_t h3 = __float_as_uint(x.w) & 0xFFFF0000u;
        float l0 = x.x - __uint_as_float(h0), l1 = x.y - __uint_as_float(h1);
        float l2 = x.z - __uint_as_float(h2), l3 = x.w - __uint_as_float(h3);
        uint2 hv, lv;
        hv.x = (h0 >> 16) | h1;
        hv.y = (h2 >> 16) | h3;
        asm("cvt.rn.bf16x2.f32 %0, %2, %1;" : "=r"(lv.x) : "f"(l0), "f"(l1));
        asm("cvt.rn.bf16x2.f32 %0, %2, %1;" : "=r"(lv.y) : "f"(l2), "f"(l3));
        dhi[i] = hv;
        dlo[i] = lv;
    }
}

// ---------------------------------------------------------------------------
// Kernel 1: GEMM C[8192,2048] = A @ B^T with pre-split bf16 planes.
// CTA 128x128, K-chunk 32, 2-stage cp.async pipeline, 8 warps (4x2).
// ---------------------------------------------------------------------------
#define TM 128
#define TN 128
#define TK 32
#define NCH (DD / TK)      // 64
#define PITCH 80           // bytes per 32-bf16 row (conflict-free ldmatrix: 5r+c mod 8)
#define PLANE (128 * PITCH)      // 10240
#define STAGE (4 * PLANE)        // 40960
#define SMEMG (2 * STAGE)        // 81920

__device__ __forceinline__ void ldmx4(uint32_t* r, uint32_t addr) {
    asm volatile("ldmatrix.sync.aligned.m8n8.x4.shared.b16 {%0,%1,%2,%3}, [%4];"
                 : "=r"(r[0]), "=r"(r[1]), "=r"(r[2]), "=r"(r[3]) : "r"(addr));
}
__device__ __forceinline__ void mma16816(float* d, const uint32_t* a,
                                         uint32_t b0, uint32_t b1) {
    asm volatile(
        "mma.sync.aligned.m16n8k16.row.col.f32.bf16.bf16.f32 "
        "{%0,%1,%2,%3}, {%4,%5,%6,%7}, {%8,%9}, {%0,%1,%2,%3};"
        : "+f"(d[0]), "+f"(d[1]), "+f"(d[2]), "+f"(d[3])
        : "r"(a[0]), "r"(a[1]), "r"(a[2]), "r"(a[3]), "r"(b0), "r"(b1));
}
__device__ __forceinline__ void cpasync16(uint32_t dst, const void* src) {
    asm volatile("cp.async.cg.shared.global [%0], [%1], 16;"
                 :: "r"(dst), "l"(src) : "memory");
}

__global__ __launch_bounds__(256, 2)
void gemm_kv_mma(void)
{
    extern __shared__ char sm[];
    const uint32_t sb = smem_u32(sm);
    const int tid = threadIdx.x;
    const int wid = tid >> 5;
    const int lane = tid & 31;
    const int wm = wid >> 1;
    const int wn = wid & 1;

    const int m0 = blockIdx.y * TM;
    const int n0 = blockIdx.x * TN;

    // cp.async mapping: thread -> row = tid>>1, two 16B chunks q = 2*(tid&1)+{0,1}
    const int crow = tid >> 1;
    const int q0 = (tid & 1) * 2;
    const __nv_bfloat16* srcA_hi = g_Ahi + (size_t)(m0 + crow) * DD + q0 * 8;
    const __nv_bfloat16* srcA_lo = g_Alo + (size_t)(m0 + crow) * DD + q0 * 8;
    const __nv_bfloat16* srcB_hi = g_Bhi + (size_t)(n0 + crow) * DD + q0 * 8;
    const __nv_bfloat16* srcB_lo = g_Blo + (size_t)(n0 + crow) * DD + q0 * 8;
    const uint32_t dbase = (uint32_t)(crow * PITCH + q0 * 16);

    float acc[2][8][4];
#pragma unroll
    for (int i = 0; i < 2; i++)
#pragma unroll
        for (int j = 0; j < 8; j++)
#pragma unroll
            for (int qq = 0; qq < 4; qq++) acc[i][j][qq] = 0.f;

    // ldmatrix base offsets (within a stage, before ksub/plane offset)
    const uint32_t a_off =
        (uint32_t)((wm * 32 + (lane & 15)) * PITCH + ((lane & 16) ? 16 : 0));
    const uint32_t b_off =
        (uint32_t)((wn * 64 + (lane & 7) + ((lane & 16) ? 8 : 0)) * PITCH +
                   ((lane & 8) ? 16 : 0));

#define ISSUE_CHUNK(c)                                                          \
    do {                                                                        \
        const int k0_ = (c) * TK;                                               \
        const uint32_t st_ = sb + ((c) & 1) * STAGE;                            \
        cpasync16(st_ + dbase,              srcA_hi + k0_);                     \
        cpasync16(st_ + dbase + 16,         srcA_hi + k0_ + 8);                 \
        cpasync16(st_ + PLANE + dbase,      srcA_lo + k0_);                     \
        cpasync16(st_ + PLANE + dbase + 16, srcA_lo + k0_ + 8);                 \
        cpasync16(st_ + 2 * PLANE + dbase,      srcB_hi + k0_);                 \
        cpasync16(st_ + 2 * PLANE + dbase + 16, srcB_hi + k0_ + 8);             \
        cpasync16(st_ + 3 * PLANE + dbase,      srcB_lo + k0_);                 \
        cpasync16(st_ + 3 * PLANE + dbase + 16, srcB_lo + k0_ + 8);             \
        asm volatile("cp.async.commit_group;" ::: "memory");                    \
    } while (0)

    ISSUE_CHUNK(0);
    ISSUE_CHUNK(1);

    for (int c = 0; c < NCH; c++) {
        asm volatile("cp.async.wait_group 1;" ::: "memory");
        __syncthreads();
        const uint32_t st = sb + (c & 1) * STAGE;

#pragma unroll
        for (int ks = 0; ks < 2; ks++) {
            const uint32_t koff = ks * 32;
            uint32_t Ahi[2][4], Alo[2][4];
#pragma unroll
            for (int mt = 0; mt < 2; mt++) {
                ldmx4(Ahi[mt], st + a_off + koff + mt * 16 * PITCH);
                ldmx4(Alo[mt], st + PLANE + a_off + koff + mt * 16 * PITCH);
            }
#pragma unroll
            for (int np = 0; np < 4; np++) {
                uint32_t Bhi[4], Blo[4];
                ldmx4(Bhi, st + 2 * PLANE + b_off + koff + np * 16 * PITCH);
                ldmx4(Blo, st + 3 * PLANE + b_off + koff + np * 16 * PITCH);
#pragma unroll
                for (int mt = 0; mt < 2; mt++) {
                    mma16816(acc[mt][2 * np],     Ahi[mt], Bhi[0], Bhi[1]);
                    mma16816(acc[mt][2 * np + 1], Ahi[mt], Bhi[2], Bhi[3]);
                    mma16816(acc[mt][2 * np],     Ahi[mt], Blo[0], Blo[1]);
                    mma16816(acc[mt][2 * np + 1], Ahi[mt], Blo[2], Blo[3]);
                    mma16816(acc[mt][2 * np],     Alo[mt], Bhi[0], Bhi[1]);
                    mma16816(acc[mt][2 * np + 1], Alo[mt], Bhi[2], Bhi[3]);
                }
            }
        }
        __syncthreads();
        if (c + 2 < NCH) ISSUE_CHUNK(c + 2);
    }

    // epilogue
#pragma unroll
    for (int mt = 0; mt < 2; mt++) {
        const int row = m0 + wm * 32 + mt * 16 + (lane >> 2);
#pragma unroll
        for (int nt = 0; nt < 8; nt++) {
            const int col = n0 + wn * 64 + nt * 8 + 2 * (lane & 3);
            float* p0 = g_proj + (size_t)row * DD + col;
            float* p1 = g_proj + (size_t)(row + 8) * DD + col;
            *reinterpret_cast<float2*>(p0) = make_float2(acc[mt][nt][0], acc[mt][nt][1]);
            *reinterpret_cast<float2*>(p1) = make_float2(acc[mt][nt][2], acc[mt][nt][3]);
        }
    }
}

// ---------------------------------------------------------------------------
// Kernel 2: beta/gamma logits. Block = 32 rows x 32 outputs, 2x2 per thread.
// ---------------------------------------------------------------------------
__global__ __launch_bounds__(256)
void proj_bg(const float* __restrict__ A,
             const float* __restrict__ b_w,
             const float* __restrict__ ts_w,
             const float* __restrict__ b_b,
             const float* __restrict__ ts_b)
{
    __shared__ float As[32][128];
    __shared__ float Ws[32][129];

    const int rb = blockIdx.x * 32;
    const int tid = threadIdx.x;
    const int r0 = (tid >> 4) * 2;      // 0,2,..,30
    const int j0 = (tid & 15) * 2;      // 0,2,..,30
    float a00 = 0.f, a01 = 0.f, a10 = 0.f, a11 = 0.f;

    for (int k0 = 0; k0 < DD; k0 += 128) {
        __syncthreads();
        for (int i = tid; i < 32 * 128; i += 256) {
            int row = i >> 7, col = i & 127;
            As[row][col] = A[(size_t)(rb + row) * DD + k0 + col];
            Ws[row][col] = (row < 16) ? b_w[(size_t)row * DD + k0 + col]
                                      : ts_w[(size_t)(row - 16) * DD + k0 + col];
        }
        __syncthreads();
#pragma unroll 4
        for (int d = 0; d < 128; d++) {
            float x0 = As[r0][d], x1 = As[r0 + 1][d];
            float w0 = Ws[j0][d], w1 = Ws[j0 + 1][d];
            a00 = fmaf(x0, w0, a00);
            a01 = fmaf(x0, w1, a01);
            a10 = fmaf(x1, w0, a10);
            a11 = fmaf(x1, w1, a11);
        }
    }

    float bias0 = (j0 < 16) ? b_b[j0] : ts_b[j0 - 16];
    float bias1 = (j0 + 1 < 16) ? b_b[j0 + 1] : ts_b[j0 + 1 - 16];
    g_bg[(size_t)(rb + r0) * 32 + j0]         = a00 + bias0;
    g_bg[(size_t)(rb + r0) * 32 + j0 + 1]     = a01 + bias1;
    g_bg[(size_t)(rb + r0 + 1) * 32 + j0]     = a10 + bias0;
    g_bg[(size_t)(rb + r0 + 1) * 32 + j0 + 1] = a11 + bias1;
}

// ---------------------------------------------------------------------------
// Kernel 3: recurrence, 128 threads: lane pairs split DK (32 cols each).
// ---------------------------------------------------------------------------
#define CH 32
#define KROW 72   // floats per staged k row; half0 cols [0,32), half1 [36,68)

__global__ __launch_bounds__(128)
void recurrent_update(const float* __restrict__ W_old,
                      const float* __restrict__ hd,
                      float* __restrict__ out)
{
    const int bh = blockIdx.x;
    const int b = bh >> 4;
    const int h = bh & 15;
    const int tid = threadIdx.x;
    const int v = tid >> 1;
    const int half = tid & 1;
    const int cb = half ? 36 : 0;

    __shared__ float ks[CH][KROW];
    __shared__ float vs[CH][DKK];
    __shared__ float betas[CH], gammas[CH], ninv[CH];

    float W[32];
    const float* wrow = W_old + ((size_t)bh * DKK + v) * DKK + half * 32;
#pragma unroll
    for (int d = 0; d < 32; d += 4) {
        float4 t = *reinterpret_cast<const float4*>(&wrow[d]);
        W[d] = t.x; W[d+1] = t.y; W[d+2] = t.z; W[d+3] = t.w;
    }
    const float hdl = hd[h];

    for (int t0 = 0; t0 < TT; t0 += CH) {
        __syncthreads();
        for (int i = tid; i < CH * DKK; i += 128) {
            int s = i >> 6, d = i & 63;
            int col = d + ((d >= 32) ? 4 : 0);
            size_t row = (size_t)(b * TT + t0 + s) * DD;
            ks[s][col] = g_proj[row + h * DKK + d];
            vs[s][d] = g_proj[row + 1024 + h * DKK + d];
        }
        __syncthreads();
        if (tid < CH) {
            int s = tid;
            float nsq = 0.f;
#pragma unroll
            for (int d = 0; d < 32; d++) {
                float x = ks[s][d], y = ks[s][36 + d];
                nsq = fmaf(x, x, nsq);
                nsq = fmaf(y, y, nsq);
            }
            ninv[s] = rsqrtf(fmaxf(nsq, 1e-24f));
            size_t brow = (size_t)(b * TT + t0 + s) * 32;
            betas[s] = 1.f / (1.f + expf(-g_bg[brow + h]));
            gammas[s] = 1.f / (1.f + expf(-(g_bg[brow + 16 + h] + hdl)));
        }
        __syncthreads();
        for (int i = tid; i < CH * DKK; i += 128) {
            int s = i >> 6, d = i & 63;
            int col = d + ((d >= 32) ? 4 : 0);
            ks[s][col] *= ninv[s];
        }
        __syncthreads();

        for (int s = 0; s < CH; s++) {
            float kr[32];
#pragma unroll
            for (int d = 0; d < 32; d += 4) {
                float4 t = *reinterpret_cast<const float4*>(&ks[s][cb + d]);
                kr[d] = t.x; kr[d+1] = t.y; kr[d+2] = t.z; kr[d+3] = t.w;
            }
            float a0 = 0.f, a1 = 0.f, a2 = 0.f, a3 = 0.f;
#pragma unroll
            for (int d = 0; d < 32; d += 4) {
                a0 = fmaf(W[d],     kr[d],     a0);
                a1 = fmaf(W[d + 1], kr[d + 1], a1);
                a2 = fmaf(W[d + 2], kr[d + 2], a2);
                a3 = fmaf(W[d + 3], kr[d + 3], a3);
            }
            float y = (a0 + a1) + (a2 + a3);
            y += __shfl_xor_sync(0xffffffffu, y, 1);
            float c = betas[s] * (vs[s][v] - y);
            float g = gammas[s];
#pragma unroll
            for (int d = 0; d < 32; d++)
                W[d] = fmaf(c, kr[d], g * W[d]);
        }
    }

    float* orow = out + ((size_t)bh * DKK + v) * DKK + half * 32;
#pragma unroll
    for (int d = 0; d < 32; d += 4) {
        float4 t = make_float4(W[d], W[d+1], W[d+2], W[d+3]);
        *reinterpret_cast<float4*>(&orow[d]) = t;
    }
}

// ---------------------------------------------------------------------------
extern "C" void kernel_launch(void* const* d_in, const int* in_sizes, int n_in,
                              void* d_out, int out_size)
{
    const float* W_old   = (const float*)d_in[0];
    const float* content = (const float*)d_in[1];
    const float* k_w     = (const float*)d_in[2];
    const float* v_w     = (const float*)d_in[3];
    const float* b_w     = (const float*)d_in[4];
    const float* b_b     = (const float*)d_in[5];
    const float* ts_w    = (const float*)d_in[6];
    const float* ts_b    = (const float*)d_in[7];
    const float* hd      = (const float*)d_in[8];
    float* out = (float*)d_out;

    // device-global plane pointers
    __nv_bfloat16 *ahi, *alo, *bhi, *blo;
    cudaGetSymbolAddress((void**)&ahi, g_Ahi);
    cudaGetSymbolAddress((void**)&alo, g_Alo);
    cudaGetSymbolAddress((void**)&bhi, g_Bhi);
    cudaGetSymbolAddress((void**)&blo, g_Blo);

    // prepass: split fp32 -> bf16 hi/lo
    cvt_split_kernel<<<2048, 256>>>((const float4*)content,
                                    (uint2*)ahi, (uint2*)alo, 8192 * 2048 / 4);
    cvt_split_kernel<<<1024, 256>>>((const float4*)k_w,
                                    (uint2*)bhi, (uint2*)blo, 1024 * 2048 / 4);
    cvt_split_kernel<<<1024, 256>>>((const float4*)v_w,
                                    (uint2*)(bhi + 1024 * 2048),
                                    (uint2*)(blo + 1024 * 2048), 1024 * 2048 / 4);

    cudaFuncSetAttribute(gemm_kv_mma, cudaFuncAttributeMaxDynamicSharedMemorySize,
                         SMEMG);
    dim3 g1(DD / TN, 8192 / TM);   // (16, 64)
    gemm_kv_mma<<<g1, 256, SMEMG>>>();
    proj_bg<<<256, 256>>>(content, b_w, ts_w, b_b, ts_b);
    recurrent_update<<<BB * HH, 128>>>(W_old, hd, out);
}

// round 5
// speedup vs baseline: 2.1913x; 1.0152x over previous
#include <cuda_runtime.h>
#include <cuda_bf16.h>
#include <math.h>
#include <stdint.h>

// Problem constants
#define BB 32
#define TT 256
#define DD 2048
#define HH 16
#define DKK 64

__device__ float g_proj[8192 * 2048];   // k|v projections (B*T, 2048)
__device__ float g_bg[8192 * 32];       // beta logits (0..15), gamma logits (16..31)

// pre-split bf16 planes
__device__ __nv_bfloat16 g_Ahi[8192 * 2048];
__device__ __nv_bfloat16 g_Alo[8192 * 2048];
__device__ __nv_bfloat16 g_Bhi[2048 * 2048];   // rows 0..1023 = k_w, 1024..2047 = v_w
__device__ __nv_bfloat16 g_Blo[2048 * 2048];

__device__ __forceinline__ uint32_t smem_u32(const void* p) {
    uint32_t a;
    asm("{ .reg .u64 t; cvta.to.shared.u64 t, %1; cvt.u32.u64 %0, t; }" : "=r"(a) : "l"(p));
    return a;
}

// ---------------------------------------------------------------------------
// Kernel 0: split fp32 -> bf16 hi/lo planes (fused: content + k_w + v_w)
// content: 4M float4 -> g_Ahi/g_Alo ; k_w: 512K -> g_Bhi/lo[0] ; v_w -> [+512K]
// ---------------------------------------------------------------------------
#define N4_A (8192 * 2048 / 4)
#define N4_W (1024 * 2048 / 4)

__global__ __launch_bounds__(256)
void cvt_split_all(const float4* __restrict__ content,
                   const float4* __restrict__ kw,
                   const float4* __restrict__ vw)
{
    int i = blockIdx.x * blockDim.x + threadIdx.x;
    const int total = N4_A + 2 * N4_W;
    const int stride = gridDim.x * blockDim.x;
    for (; i < total; i += stride) {
        const float4* src;
        uint2 *dhi, *dlo;
        int j;
        if (i < N4_A) {
            j = i; src = content;
            dhi = (uint2*)g_Ahi; dlo = (uint2*)g_Alo;
        } else if (i < N4_A + N4_W) {
            j = i - N4_A; src = kw;
            dhi = (uint2*)g_Bhi; dlo = (uint2*)g_Blo;
        } else {
            j = i - N4_A - N4_W; src = vw;
            dhi = (uint2*)(g_Bhi + 1024 * 2048); dlo = (uint2*)(g_Blo + 1024 * 2048);
        }
        float4 x = src[j];
        uint32_t h0 = __float_as_uint(x.x) & 0xFFFF0000u;
        uint32_t h1 = __float_as_uint(x.y) & 0xFFFF0000u;
        uint32_t h2 = __float_as_uint(x.z) & 0xFFFF0000u;
        uint32_t h3 = __float_as_uint(x.w) & 0xFFFF0000u;
        float l0 = x.x - __uint_as_float(h0), l1 = x.y - __uint_as_float(h1);
        float l2 = x.z - __uint_as_float(h2), l3 = x.w - __uint_as_float(h3);
        uint2 hv, lv;
        hv.x = (h0 >> 16) | h1;
        hv.y = (h2 >> 16) | h3;
        asm("cvt.rn.bf16x2.f32 %0, %2, %1;" : "=r"(lv.x) : "f"(l0), "f"(l1));
        asm("cvt.rn.bf16x2.f32 %0, %2, %1;" : "=r"(lv.y) : "f"(l2), "f"(l3));
        dhi[j] = hv;
        dlo[j] = lv;
    }
}

// ---------------------------------------------------------------------------
// Kernel 1: GEMM C[8192,2048] = A @ B^T, pre-split bf16 planes.
// CTA 128x128, K-chunk 32, 2-stage cp.async pipeline, 8 warps (4x2).
// mma stream ordered at dependency distance 4.
// ---------------------------------------------------------------------------
#define TM 128
#define TN 128
#define TK 32
#define NCH (DD / TK)      // 64
#define PITCH 80
#define PLANE (128 * PITCH)
#define STAGE (4 * PLANE)
#define SMEMG (2 * STAGE)

__device__ __forceinline__ void ldmx4(uint32_t* r, uint32_t addr) {
    asm volatile("ldmatrix.sync.aligned.m8n8.x4.shared.b16 {%0,%1,%2,%3}, [%4];"
                 : "=r"(r[0]), "=r"(r[1]), "=r"(r[2]), "=r"(r[3]) : "r"(addr));
}
__device__ __forceinline__ void mma16816(float* d, const uint32_t* a,
                                         uint32_t b0, uint32_t b1) {
    asm volatile(
        "mma.sync.aligned.m16n8k16.row.col.f32.bf16.bf16.f32 "
        "{%0,%1,%2,%3}, {%4,%5,%6,%7}, {%8,%9}, {%0,%1,%2,%3};"
        : "+f"(d[0]), "+f"(d[1]), "+f"(d[2]), "+f"(d[3])
        : "r"(a[0]), "r"(a[1]), "r"(a[2]), "r"(a[3]), "r"(b0), "r"(b1));
}
__device__ __forceinline__ void cpasync16(uint32_t dst, const void* src) {
    asm volatile("cp.async.cg.shared.global [%0], [%1], 16;"
                 :: "r"(dst), "l"(src) : "memory");
}

__global__ __launch_bounds__(256, 2)
void gemm_kv_mma(void)
{
    extern __shared__ char sm[];
    const uint32_t sb = smem_u32(sm);
    const int tid = threadIdx.x;
    const int wid = tid >> 5;
    const int lane = tid & 31;
    const int wm = wid >> 1;
    const int wn = wid & 1;

    const int m0 = blockIdx.y * TM;
    const int n0 = blockIdx.x * TN;

    const int crow = tid >> 1;
    const int q0 = (tid & 1) * 2;
    const __nv_bfloat16* srcA_hi = g_Ahi + (size_t)(m0 + crow) * DD + q0 * 8;
    const __nv_bfloat16* srcA_lo = g_Alo + (size_t)(m0 + crow) * DD + q0 * 8;
    const __nv_bfloat16* srcB_hi = g_Bhi + (size_t)(n0 + crow) * DD + q0 * 8;
    const __nv_bfloat16* srcB_lo = g_Blo + (size_t)(n0 + crow) * DD + q0 * 8;
    const uint32_t dbase = (uint32_t)(crow * PITCH + q0 * 16);

    float acc[2][8][4];
#pragma unroll
    for (int i = 0; i < 2; i++)
#pragma unroll
        for (int j = 0; j < 8; j++)
#pragma unroll
            for (int qq = 0; qq < 4; qq++) acc[i][j][qq] = 0.f;

    const uint32_t a_off =
        (uint32_t)((wm * 32 + (lane & 15)) * PITCH + ((lane & 16) ? 16 : 0));
    const uint32_t b_off =
        (uint32_t)((wn * 64 + (lane & 7) + ((lane & 16) ? 8 : 0)) * PITCH +
                   ((lane & 8) ? 16 : 0));

#define ISSUE_CHUNK(c)                                                          \
    do {                                                                        \
        const int k0_ = (c) * TK;                                               \
        const uint32_t st_ = sb + ((c) & 1) * STAGE;                            \
        cpasync16(st_ + dbase,              srcA_hi + k0_);                     \
        cpasync16(st_ + dbase + 16,         srcA_hi + k0_ + 8);                 \
        cpasync16(st_ + PLANE + dbase,      srcA_lo + k0_);                     \
        cpasync16(st_ + PLANE + dbase + 16, srcA_lo + k0_ + 8);                 \
        cpasync16(st_ + 2 * PLANE + dbase,      srcB_hi + k0_);                 \
        cpasync16(st_ + 2 * PLANE + dbase + 16, srcB_hi + k0_ + 8);             \
        cpasync16(st_ + 3 * PLANE + dbase,      srcB_lo + k0_);                 \
        cpasync16(st_ + 3 * PLANE + dbase + 16, srcB_lo + k0_ + 8);             \
        asm volatile("cp.async.commit_group;" ::: "memory");                    \
    } while (0)

    ISSUE_CHUNK(0);
    ISSUE_CHUNK(1);

    for (int c = 0; c < NCH; c++) {
        asm volatile("cp.async.wait_group 1;" ::: "memory");
        __syncthreads();
        const uint32_t st = sb + (c & 1) * STAGE;

#pragma unroll
        for (int ks = 0; ks < 2; ks++) {
            const uint32_t koff = ks * 32;
            uint32_t Ahi[2][4], Alo[2][4];
#pragma unroll
            for (int mt = 0; mt < 2; mt++) {
                ldmx4(Ahi[mt], st + a_off + koff + mt * 16 * PITCH);
                ldmx4(Alo[mt], st + PLANE + a_off + koff + mt * 16 * PITCH);
            }
#pragma unroll
            for (int np = 0; np < 4; np++) {
                uint32_t Bhi[4], Blo[4];
                ldmx4(Bhi, st + 2 * PLANE + b_off + koff + np * 16 * PITCH);
                ldmx4(Blo, st + 3 * PLANE + b_off + koff + np * 16 * PITCH);
                // group 1: hi*hi — 4 independent accumulators
                mma16816(acc[0][2 * np],     Ahi[0], Bhi[0], Bhi[1]);
                mma16816(acc[1][2 * np],     Ahi[1], Bhi[0], Bhi[1]);
                mma16816(acc[0][2 * np + 1], Ahi[0], Bhi[2], Bhi[3]);
                mma16816(acc[1][2 * np + 1], Ahi[1], Bhi[2], Bhi[3]);
                // group 2: hi*lo
                mma16816(acc[0][2 * np],     Ahi[0], Blo[0], Blo[1]);
                mma16816(acc[1][2 * np],     Ahi[1], Blo[0], Blo[1]);
                mma16816(acc[0][2 * np + 1], Ahi[0], Blo[2], Blo[3]);
                mma16816(acc[1][2 * np + 1], Ahi[1], Blo[2], Blo[3]);
                // group 3: lo*hi
                mma16816(acc[0][2 * np],     Alo[0], Bhi[0], Bhi[1]);
                mma16816(acc[1][2 * np],     Alo[1], Bhi[0], Bhi[1]);
                mma16816(acc[0][2 * np + 1], Alo[0], Bhi[2], Bhi[3]);
                mma16816(acc[1][2 * np + 1], Alo[1], Bhi[2], Bhi[3]);
            }
        }
        __syncthreads();
        if (c + 2 < NCH) ISSUE_CHUNK(c + 2);
    }

    // epilogue
#pragma unroll
    for (int mt = 0; mt < 2; mt++) {
        const int row = m0 + wm * 32 + mt * 16 + (lane >> 2);
#pragma unroll
        for (int nt = 0; nt < 8; nt++) {
            const int col = n0 + wn * 64 + nt * 8 + 2 * (lane & 3);
            float* p0 = g_proj + (size_t)row * DD + col;
            float* p1 = g_proj + (size_t)(row + 8) * DD + col;
            *reinterpret_cast<float2*>(p0) = make_float2(acc[mt][nt][0], acc[mt][nt][1]);
            *reinterpret_cast<float2*>(p1) = make_float2(acc[mt][nt][2], acc[mt][nt][3]);
        }
    }
}

// ---------------------------------------------------------------------------
// Kernel 2: beta/gamma logits. Block = 32 rows x 32 outputs, 2x2 per thread.
// ---------------------------------------------------------------------------
__global__ __launch_bounds__(256)
void proj_bg(const float* __restrict__ A,
             const float* __restrict__ b_w,
             const float* __restrict__ ts_w,
             const float* __restrict__ b_b,
             const float* __restrict__ ts_b)
{
    __shared__ float As[32][128];
    __shared__ float Ws[32][129];

    const int rb = blockIdx.x * 32;
    const int tid = threadIdx.x;
    const int r0 = (tid >> 4) * 2;
    const int j0 = (tid & 15) * 2;
    float a00 = 0.f, a01 = 0.f, a10 = 0.f, a11 = 0.f;

    for (int k0 = 0; k0 < DD; k0 += 128) {
        __syncthreads();
        for (int i = tid; i < 32 * 128; i += 256) {
            int row = i >> 7, col = i & 127;
            As[row][col] = A[(size_t)(rb + row) * DD + k0 + col];
            Ws[row][col] = (row < 16) ? b_w[(size_t)row * DD + k0 + col]
                                      : ts_w[(size_t)(row - 16) * DD + k0 + col];
        }
        __syncthreads();
#pragma unroll 4
        for (int d = 0; d < 128; d++) {
            float x0 = As[r0][d], x1 = As[r0 + 1][d];
            float w0 = Ws[j0][d], w1 = Ws[j0 + 1][d];
            a00 = fmaf(x0, w0, a00);
            a01 = fmaf(x0, w1, a01);
            a10 = fmaf(x1, w0, a10);
            a11 = fmaf(x1, w1, a11);
        }
    }

    float bias0 = (j0 < 16) ? b_b[j0] : ts_b[j0 - 16];
    float bias1 = (j0 + 1 < 16) ? b_b[j0 + 1] : ts_b[j0 + 1 - 16];
    g_bg[(size_t)(rb + r0) * 32 + j0]         = a00 + bias0;
    g_bg[(size_t)(rb + r0) * 32 + j0 + 1]     = a01 + bias1;
    g_bg[(size_t)(rb + r0 + 1) * 32 + j0]     = a10 + bias0;
    g_bg[(size_t)(rb + r0 + 1) * 32 + j0 + 1] = a11 + bias1;
}

// ---------------------------------------------------------------------------
// Kernel 3: recurrence, 128 threads: lane pairs split DK (32 cols each).
// ---------------------------------------------------------------------------
#define CH 32
#define KROW 72

__global__ __launch_bounds__(128)
void recurrent_update(const float* __restrict__ W_old,
                      const float* __restrict__ hd,
                      float* __restrict__ out)
{
    const int bh = blockIdx.x;
    const int b = bh >> 4;
    const int h = bh & 15;
    const int tid = threadIdx.x;
    const int v = tid >> 1;
    const int half = tid & 1;
    const int cb = half ? 36 : 0;

    __shared__ float ks[CH][KROW];
    __shared__ float vs[CH][DKK];
    __shared__ float betas[CH], gammas[CH], ninv[CH];

    float W[32];
    const float* wrow = W_old + ((size_t)bh * DKK + v) * DKK + half * 32;
#pragma unroll
    for (int d = 0; d < 32; d += 4) {
        float4 t = *reinterpret_cast<const float4*>(&wrow[d]);
        W[d] = t.x; W[d+1] = t.y; W[d+2] = t.z; W[d+3] = t.w;
    }
    const float hdl = hd[h];

    for (int t0 = 0; t0 < TT; t0 += CH) {
        __syncthreads();
        for (int i = tid; i < CH * DKK; i += 128) {
            int s = i >> 6, d = i & 63;
            int col = d + ((d >= 32) ? 4 : 0);
            size_t row = (size_t)(b * TT + t0 + s) * DD;
            ks[s][col] = g_proj[row + h * DKK + d];
            vs[s][d] = g_proj[row + 1024 + h * DKK + d];
        }
        __syncthreads();
        if (tid < CH) {
            int s = tid;
            float nsq = 0.f;
#pragma unroll
            for (int d = 0; d < 32; d++) {
                float x = ks[s][d], y = ks[s][36 + d];
                nsq = fmaf(x, x, nsq);
                nsq = fmaf(y, y, nsq);
            }
            ninv[s] = rsqrtf(fmaxf(nsq, 1e-24f));
            size_t brow = (size_t)(b * TT + t0 + s) * 32;
            betas[s] = 1.f / (1.f + expf(-g_bg[brow + h]));
            gammas[s] = 1.f / (1.f + expf(-(g_bg[brow + 16 + h] + hdl)));
        }
        __syncthreads();
        for (int i = tid; i < CH * DKK; i += 128) {
            int s = i >> 6, d = i & 63;
            int col = d + ((d >= 32) ? 4 : 0);
            ks[s][col] *= ninv[s];
        }
        __syncthreads();

        for (int s = 0; s < CH; s++) {
            float kr[32];
#pragma unroll
            for (int d = 0; d < 32; d += 4) {
                float4 t = *reinterpret_cast<const float4*>(&ks[s][cb + d]);
                kr[d] = t.x; kr[d+1] = t.y; kr[d+2] = t.z; kr[d+3] = t.w;
            }
            float a0 = 0.f, a1 = 0.f, a2 = 0.f, a3 = 0.f;
#pragma unroll
            for (int d = 0; d < 32; d += 4) {
                a0 = fmaf(W[d],     kr[d],     a0);
                a1 = fmaf(W[d + 1], kr[d + 1], a1);
                a2 = fmaf(W[d + 2], kr[d + 2], a2);
                a3 = fmaf(W[d + 3], kr[d + 3], a3);
            }
            float y = (a0 + a1) + (a2 + a3);
            y += __shfl_xor_sync(0xffffffffu, y, 1);
            float c = betas[s] * (vs[s][v] - y);
            float g = gammas[s];
#pragma unroll
            for (int d = 0; d < 32; d++)
                W[d] = fmaf(c, kr[d], g * W[d]);
        }
    }

    float* orow = out + ((size_t)bh * DKK + v) * DKK + half * 32;
#pragma unroll
    for (int d = 0; d < 32; d += 4) {
        float4 t = make_float4(W[d], W[d+1], W[d+2], W[d+3]);
        *reinterpret_cast<float4*>(&orow[d]) = t;
    }
}

// ---------------------------------------------------------------------------
extern "C" void kernel_launch(void* const* d_in, const int* in_sizes, int n_in,
                              void* d_out, int out_size)
{
    const float* W_old   = (const float*)d_in[0];
    const float* content = (const float*)d_in[1];
    const float* k_w     = (const float*)d_in[2];
    const float* v_w     = (const float*)d_in[3];
    const float* b_w     = (const float*)d_in[4];
    const float* b_b     = (const float*)d_in[5];
    const float* ts_w    = (const float*)d_in[6];
    const float* ts_b    = (const float*)d_in[7];
    const float* hd      = (const float*)d_in[8];
    float* out = (float*)d_out;

    cvt_split_all<<<4096, 256>>>((const float4*)content,
                                 (const float4*)k_w, (const float4*)v_w);

    cudaFuncSetAttribute(gemm_kv_mma, cudaFuncAttributeMaxDynamicSharedMemorySize,
                         SMEMG);
    dim3 g1(DD / TN, 8192 / TM);   // (16, 64)
    gemm_kv_mma<<<g1, 256, SMEMG>>>();
    proj_bg<<<256, 256>>>(content, b_w, ts_w, b_b, ts_b);
    recurrent_update<<<BB * HH, 128>>>(W_old, hd, out);
}

// round 6
// speedup vs baseline: 2.3808x; 1.0865x over previous
#include <cuda_runtime.h>
#include <cuda_bf16.h>
#include <math.h>
#include <stdint.h>

// Problem constants
#define BB 32
#define TT 256
#define DD 2048
#define HH 16
#define DKK 64

typedef unsigned long long u64;

__device__ float g_proj[8192 * 2048];   // k|v projections (B*T, 2048)
__device__ float g_bg[8192 * 32];       // beta logits (0..15), gamma logits (16..31)

// pre-split bf16 planes
__device__ __nv_bfloat16 g_Ahi[8192 * 2048];
__device__ __nv_bfloat16 g_Alo[8192 * 2048];
__device__ __nv_bfloat16 g_Bhi[2048 * 2048];   // rows 0..1023 = k_w, 1024..2047 = v_w
__device__ __nv_bfloat16 g_Blo[2048 * 2048];

__device__ __forceinline__ uint32_t smem_u32(const void* p) {
    uint32_t a;
    asm("{ .reg .u64 t; cvta.to.shared.u64 t, %1; cvt.u32.u64 %0, t; }" : "=r"(a) : "l"(p));
    return a;
}

// packed f32x2 helpers
#define FMA2(d, a, b, c2) \
    asm("fma.rn.f32x2 %0, %1, %2, %3;" : "=l"(d) : "l"(a), "l"(b), "l"(c2))
#define MUL2(d, a, b) \
    asm("mul.rn.f32x2 %0, %1, %2;" : "=l"(d) : "l"(a), "l"(b))
__device__ __forceinline__ u64 packdup(float x) {
    u64 r; uint32_t xu = __float_as_uint(x);
    asm("mov.b64 %0, {%1, %1};" : "=l"(r) : "r"(xu));
    return r;
}
__device__ __forceinline__ void unpack2(u64 p, float& lo, float& hi) {
    uint32_t a, b;
    asm("mov.b64 {%0, %1}, %2;" : "=r"(a), "=r"(b) : "l"(p));
    lo = __uint_as_float(a); hi = __uint_as_float(b);
}

// ---------------------------------------------------------------------------
// Kernel 0: split fp32 -> bf16 hi/lo planes (fused: content + k_w + v_w)
// ---------------------------------------------------------------------------
#define N4_A (8192 * 2048 / 4)
#define N4_W (1024 * 2048 / 4)

__global__ __launch_bounds__(256)
void cvt_split_all(const float4* __restrict__ content,
                   const float4* __restrict__ kw,
                   const float4* __restrict__ vw)
{
    int i = blockIdx.x * blockDim.x + threadIdx.x;
    const int total = N4_A + 2 * N4_W;
    const int stride = gridDim.x * blockDim.x;
    for (; i < total; i += stride) {
        const float4* src;
        uint2 *dhi, *dlo;
        int j;
        if (i < N4_A) {
            j = i; src = content;
            dhi = (uint2*)g_Ahi; dlo = (uint2*)g_Alo;
        } else if (i < N4_A + N4_W) {
            j = i - N4_A; src = kw;
            dhi = (uint2*)g_Bhi; dlo = (uint2*)g_Blo;
        } else {
            j = i - N4_A - N4_W; src = vw;
            dhi = (uint2*)(g_Bhi + 1024 * 2048); dlo = (uint2*)(g_Blo + 1024 * 2048);
        }
        float4 x = src[j];
        uint32_t h0 = __float_as_uint(x.x) & 0xFFFF0000u;
        uint32_t h1 = __float_as_uint(x.y) & 0xFFFF0000u;
        uint32_t h2 = __float_as_uint(x.z) & 0xFFFF0000u;
        uint32_t h3 = __float_as_uint(x.w) & 0xFFFF0000u;
        float l0 = x.x - __uint_as_float(h0), l1 = x.y - __uint_as_float(h1);
        float l2 = x.z - __uint_as_float(h2), l3 = x.w - __uint_as_float(h3);
        uint2 hv, lv;
        hv.x = (h0 >> 16) | h1;
        hv.y = (h2 >> 16) | h3;
        asm("cvt.rn.bf16x2.f32 %0, %2, %1;" : "=r"(lv.x) : "f"(l0), "f"(l1));
        asm("cvt.rn.bf16x2.f32 %0, %2, %1;" : "=r"(lv.y) : "f"(l2), "f"(l3));
        dhi[j] = hv;
        dlo[j] = lv;
    }
}

// ---------------------------------------------------------------------------
// Kernel 1: GEMM, pre-split bf16 planes.
// CTA 128x128, K-chunk 16, 4-stage cp.async pipeline, ONE sync per chunk.
// ---------------------------------------------------------------------------
#define TM 128
#define TN 128
#define TK 16
#define NCH (DD / TK)        // 128
#define PITCH 48             // 16 bf16 = 32B data + 16B pad; 3r+c mod 8 bijective
#define PLANE (128 * PITCH)  // 6144
#define STAGE (4 * PLANE)    // 24576
#define NSTG 4
#define SMEMG (NSTG * STAGE) // 98304 -> 2 CTAs/SM

__device__ __forceinline__ void ldmx4(uint32_t* r, uint32_t addr) {
    asm volatile("ldmatrix.sync.aligned.m8n8.x4.shared.b16 {%0,%1,%2,%3}, [%4];"
                 : "=r"(r[0]), "=r"(r[1]), "=r"(r[2]), "=r"(r[3]) : "r"(addr));
}
__device__ __forceinline__ void mma16816(float* d, const uint32_t* a,
                                         uint32_t b0, uint32_t b1) {
    asm volatile(
        "mma.sync.aligned.m16n8k16.row.col.f32.bf16.bf16.f32 "
        "{%0,%1,%2,%3}, {%4,%5,%6,%7}, {%8,%9}, {%0,%1,%2,%3};"
        : "+f"(d[0]), "+f"(d[1]), "+f"(d[2]), "+f"(d[3])
        : "r"(a[0]), "r"(a[1]), "r"(a[2]), "r"(a[3]), "r"(b0), "r"(b1));
}
__device__ __forceinline__ void cpasync16(uint32_t dst, const void* src) {
    asm volatile("cp.async.cg.shared.global [%0], [%1], 16;"
                 :: "r"(dst), "l"(src) : "memory");
}

__global__ __launch_bounds__(256, 2)
void gemm_kv_mma(void)
{
    extern __shared__ char sm[];
    const uint32_t sb = smem_u32(sm);
    const int tid = threadIdx.x;
    const int wid = tid >> 5;
    const int lane = tid & 31;
    const int wm = wid >> 1;
    const int wn = wid & 1;

    const int m0 = blockIdx.y * TM;
    const int n0 = blockIdx.x * TN;

    // cp.async mapping: row = tid>>1, q = tid&1 selects 16B half of the 32B row
    const int crow = tid >> 1;
    const int q = tid & 1;
    const __nv_bfloat16* srcA_hi = g_Ahi + (size_t)(m0 + crow) * DD + q * 8;
    const __nv_bfloat16* srcA_lo = g_Alo + (size_t)(m0 + crow) * DD + q * 8;
    const __nv_bfloat16* srcB_hi = g_Bhi + (size_t)(n0 + crow) * DD + q * 8;
    const __nv_bfloat16* srcB_lo = g_Blo + (size_t)(n0 + crow) * DD + q * 8;
    const uint32_t dbase = (uint32_t)(crow * PITCH + q * 16);

    float acc[2][8][4];
#pragma unroll
    for (int i = 0; i < 2; i++)
#pragma unroll
        for (int j = 0; j < 8; j++)
#pragma unroll
            for (int qq = 0; qq < 4; qq++) acc[i][j][qq] = 0.f;

    const uint32_t a_off =
        (uint32_t)((wm * 32 + (lane & 15)) * PITCH + ((lane & 16) ? 16 : 0));
    const uint32_t b_off =
        (uint32_t)((wn * 64 + (lane & 7) + ((lane & 16) ? 8 : 0)) * PITCH +
                   ((lane & 8) ? 16 : 0));

#define ISSUE_CHUNK(c)                                                          \
    do {                                                                        \
        const int k0_ = (c) * TK;                                               \
        const uint32_t st_ = sb + ((c) & (NSTG - 1)) * STAGE;                   \
        cpasync16(st_ + dbase,             srcA_hi + k0_);                      \
        cpasync16(st_ + PLANE + dbase,     srcA_lo + k0_);                      \
        cpasync16(st_ + 2 * PLANE + dbase, srcB_hi + k0_);                      \
        cpasync16(st_ + 3 * PLANE + dbase, srcB_lo + k0_);                      \
        asm volatile("cp.async.commit_group;" ::: "memory");                    \
    } while (0)

    ISSUE_CHUNK(0);
    ISSUE_CHUNK(1);
    ISSUE_CHUNK(2);

    for (int c = 0; c < NCH; c++) {
        asm volatile("cp.async.wait_group 2;" ::: "memory");
        __syncthreads();
        const uint32_t st = sb + (c & (NSTG - 1)) * STAGE;

        uint32_t Ahi[2][4], Alo[2][4];
#pragma unroll
        for (int mt = 0; mt < 2; mt++) {
            ldmx4(Ahi[mt], st + a_off + mt * 16 * PITCH);
            ldmx4(Alo[mt], st + PLANE + a_off + mt * 16 * PITCH);
        }
#pragma unroll
        for (int np = 0; np < 4; np++) {
            uint32_t Bhi[4], Blo[4];
            ldmx4(Bhi, st + 2 * PLANE + b_off + np * 16 * PITCH);
            ldmx4(Blo, st + 3 * PLANE + b_off + np * 16 * PITCH);
            mma16816(acc[0][2 * np],     Ahi[0], Bhi[0], Bhi[1]);
            mma16816(acc[1][2 * np],     Ahi[1], Bhi[0], Bhi[1]);
            mma16816(acc[0][2 * np + 1], Ahi[0], Bhi[2], Bhi[3]);
            mma16816(acc[1][2 * np + 1], Ahi[1], Bhi[2], Bhi[3]);
            mma16816(acc[0][2 * np],     Ahi[0], Blo[0], Blo[1]);
            mma16816(acc[1][2 * np],     Ahi[1], Blo[0], Blo[1]);
            mma16816(acc[0][2 * np + 1], Ahi[0], Blo[2], Blo[3]);
            mma16816(acc[1][2 * np + 1], Ahi[1], Blo[2], Blo[3]);
            mma16816(acc[0][2 * np],     Alo[0], Bhi[0], Bhi[1]);
            mma16816(acc[1][2 * np],     Alo[1], Bhi[0], Bhi[1]);
            mma16816(acc[0][2 * np + 1], Alo[0], Bhi[2], Bhi[3]);
            mma16816(acc[1][2 * np + 1], Alo[1], Bhi[2], Bhi[3]);
        }

        if (c + 3 < NCH) {
            ISSUE_CHUNK(c + 3);
        } else {
            asm volatile("cp.async.commit_group;" ::: "memory");  // keep accounting
        }
    }

    // epilogue
#pragma unroll
    for (int mt = 0; mt < 2; mt++) {
        const int row = m0 + wm * 32 + mt * 16 + (lane >> 2);
#pragma unroll
        for (int nt = 0; nt < 8; nt++) {
            const int col = n0 + wn * 64 + nt * 8 + 2 * (lane & 3);
            float* p0 = g_proj + (size_t)row * DD + col;
            float* p1 = g_proj + (size_t)(row + 8) * DD + col;
            *reinterpret_cast<float2*>(p0) = make_float2(acc[mt][nt][0], acc[mt][nt][1]);
            *reinterpret_cast<float2*>(p1) = make_float2(acc[mt][nt][2], acc[mt][nt][3]);
        }
    }
}

// ---------------------------------------------------------------------------
// Kernel 2: beta/gamma logits. 32 rows x 32 outputs per block, f32x2 inner.
// ---------------------------------------------------------------------------
__global__ __launch_bounds__(256)
void proj_bg(const float* __restrict__ A,
             const float* __restrict__ b_w,
             const float* __restrict__ ts_w,
             const float* __restrict__ b_b,
             const float* __restrict__ ts_b)
{
    __shared__ float As[32][128];
    __shared__ float Wt[128][34];   // transposed: (d, j), pad 2

    const int rb = blockIdx.x * 32;
    const int tid = threadIdx.x;
    const int r0 = (tid >> 4) * 2;
    const int j0 = (tid & 15) * 2;
    u64 p0 = 0, p1 = 0;

    for (int k0 = 0; k0 < DD; k0 += 128) {
        __syncthreads();
        for (int i = tid; i < 32 * 128; i += 256) {
            int row = i >> 7, col = i & 127;   // row = j index, col = d index
            As[row][col] = A[(size_t)(rb + row) * DD + k0 + col];
            Wt[col][row] = (row < 16) ? b_w[(size_t)row * DD + k0 + col]
                                      : ts_w[(size_t)(row - 16) * DD + k0 + col];
        }
        __syncthreads();
#pragma unroll 4
        for (int d = 0; d < 128; d++) {
            u64 w2 = *reinterpret_cast<const u64*>(&Wt[d][j0]);
            u64 x0 = packdup(As[r0][d]);
            u64 x1 = packdup(As[r0 + 1][d]);
            FMA2(p0, x0, w2, p0);
            FMA2(p1, x1, w2, p1);
        }
    }

    float a00, a01, a10, a11;
    unpack2(p0, a00, a01);
    unpack2(p1, a10, a11);
    float bias0 = (j0 < 16) ? b_b[j0] : ts_b[j0 - 16];
    float bias1 = (j0 + 1 < 16) ? b_b[j0 + 1] : ts_b[j0 + 1 - 16];
    g_bg[(size_t)(rb + r0) * 32 + j0]         = a00 + bias0;
    g_bg[(size_t)(rb + r0) * 32 + j0 + 1]     = a01 + bias1;
    g_bg[(size_t)(rb + r0 + 1) * 32 + j0]     = a10 + bias0;
    g_bg[(size_t)(rb + r0 + 1) * 32 + j0 + 1] = a11 + bias1;
}

// ---------------------------------------------------------------------------
// Kernel 3: recurrence, 128 threads, f32x2 packed math.
// ---------------------------------------------------------------------------
#define CH 32
#define KROW 80   // halves at float offsets 0 and 40 (both 16B aligned/row 320B)

__global__ __launch_bounds__(128)
void recurrent_update(const float* __restrict__ W_old,
                      const float* __restrict__ hd,
                      float* __restrict__ out)
{
    const int bh = blockIdx.x;
    const int b = bh >> 4;
    const int h = bh & 15;
    const int tid = threadIdx.x;
    const int v = tid >> 1;
    const int half = tid & 1;
    const int cb = half ? 40 : 0;

    __shared__ float ks[CH][KROW];
    __shared__ float vs[CH][DKK];
    __shared__ float betas[CH], gammas[CH], ninv[CH];

    u64 W2[16];
    const float* wrow = W_old + ((size_t)bh * DKK + v) * DKK + half * 32;
#pragma unroll
    for (int d = 0; d < 16; d += 2) {
        ulonglong2 t = *reinterpret_cast<const ulonglong2*>(&wrow[d * 2]);
        W2[d] = t.x; W2[d + 1] = t.y;
    }
    const float hdl = hd[h];

    for (int t0 = 0; t0 < TT; t0 += CH) {
        __syncthreads();
        for (int i = tid; i < CH * DKK; i += 128) {
            int s = i >> 6, d = i & 63;
            int col = d + ((d >= 32) ? 8 : 0);
            size_t row = (size_t)(b * TT + t0 + s) * DD;
            ks[s][col] = g_proj[row + h * DKK + d];
            vs[s][d] = g_proj[row + 1024 + h * DKK + d];
        }
        __syncthreads();
        if (tid < CH) {
            int s = tid;
            float nsq = 0.f;
#pragma unroll
            for (int d = 0; d < 32; d++) {
                float x = ks[s][d], y = ks[s][40 + d];
                nsq = fmaf(x, x, nsq);
                nsq = fmaf(y, y, nsq);
            }
            ninv[s] = rsqrtf(fmaxf(nsq, 1e-24f));
            size_t brow = (size_t)(b * TT + t0 + s) * 32;
            betas[s] = 1.f / (1.f + expf(-g_bg[brow + h]));
            gammas[s] = 1.f / (1.f + expf(-(g_bg[brow + 16 + h] + hdl)));
        }
        __syncthreads();
        for (int i = tid; i < CH * DKK; i += 128) {
            int s = i >> 6, d = i & 63;
            int col = d + ((d >= 32) ? 8 : 0);
            ks[s][col] *= ninv[s];
        }
        __syncthreads();

        for (int s = 0; s < CH; s++) {
            u64 K2[16];
#pragma unroll
            for (int d = 0; d < 16; d += 2) {
                ulonglong2 t = *reinterpret_cast<const ulonglong2*>(&ks[s][cb + d * 2]);
                K2[d] = t.x; K2[d + 1] = t.y;
            }
            u64 ac0 = 0, ac1 = 0, ac2 = 0, ac3 = 0;
#pragma unroll
            for (int d = 0; d < 16; d += 4) {
                FMA2(ac0, W2[d],     K2[d],     ac0);
                FMA2(ac1, W2[d + 1], K2[d + 1], ac1);
                FMA2(ac2, W2[d + 2], K2[d + 2], ac2);
                FMA2(ac3, W2[d + 3], K2[d + 3], ac3);
            }
            float s0, s1, s2, s3, s4, s5, s6, s7;
            unpack2(ac0, s0, s1); unpack2(ac1, s2, s3);
            unpack2(ac2, s4, s5); unpack2(ac3, s6, s7);
            float y = ((s0 + s1) + (s2 + s3)) + ((s4 + s5) + (s6 + s7));
            y += __shfl_xor_sync(0xffffffffu, y, 1);
            float c = betas[s] * (vs[s][v] - y);
            float g = gammas[s];
            u64 c2 = packdup(c), g2 = packdup(g);
#pragma unroll
            for (int d = 0; d < 16; d++) {
                u64 t;
                MUL2(t, g2, W2[d]);
                FMA2(W2[d], c2, K2[d], t);
            }
        }
    }

    float* orow = out + ((size_t)bh * DKK + v) * DKK + half * 32;
#pragma unroll
    for (int d = 0; d < 16; d += 2) {
        ulonglong2 t;
        t.x = W2[d]; t.y = W2[d + 1];
        *reinterpret_cast<ulonglong2*>(&orow[d * 2]) = t;
    }
}

// ---------------------------------------------------------------------------
extern "C" void kernel_launch(void* const* d_in, const int* in_sizes, int n_in,
                              void* d_out, int out_size)
{
    const float* W_old   = (const float*)d_in[0];
    const float* content = (const float*)d_in[1];
    const float* k_w     = (const float*)d_in[2];
    const float* v_w     = (const float*)d_in[3];
    const float* b_w     = (const float*)d_in[4];
    const float* b_b     = (const float*)d_in[5];
    const float* ts_w    = (const float*)d_in[6];
    const float* ts_b    = (const float*)d_in[7];
    const float* hd      = (const float*)d_in[8];
    float* out = (float*)d_out;

    cvt_split_all<<<4096, 256>>>((const float4*)content,
                                 (const float4*)k_w, (const float4*)v_w);

    cudaFuncSetAttribute(gemm_kv_mma, cudaFuncAttributeMaxDynamicSharedMemorySize,
                         SMEMG);
    dim3 g1(DD / TN, 8192 / TM);   // (16, 64)
    gemm_kv_mma<<<g1, 256, SMEMG>>>();
    proj_bg<<<256, 256>>>(content, b_w, ts_w, b_b, ts_b);
    recurrent_update<<<BB * HH, 128>>>(W_old, hd, out);
}

// round 7
// speedup vs baseline: 3.0050x; 1.2622x over previous
#include <cuda_runtime.h>
#include <cuda_bf16.h>
#include <cuda_fp16.h>
#include <math.h>
#include <stdint.h>

// Problem constants
#define BB 32
#define TT 256
#define DD 2048
#define HH 16
#define DKK 64

__device__ float g_proj[8192 * 2048];   // k|v projections (B*T, 2048)
__device__ float g_bg[8192 * 32];       // beta logits (0..15), gamma logits (16..31)

// fp16 operand planes
__device__ __half g_Af16[8192 * 2048];  // content, single fp16 plane
__device__ __half g_Bhi[2048 * 2048];   // weights hi; rows 0..1023 = k_w, 1024.. = v_w
__device__ __half g_Blo[2048 * 2048];   // weights residual

__device__ __forceinline__ uint32_t smem_u32(const void* p) {
    uint32_t a;
    asm("{ .reg .u64 t; cvta.to.shared.u64 t, %1; cvt.u32.u64 %0, t; }" : "=r"(a) : "l"(p));
    return a;
}

// ---------------------------------------------------------------------------
// Kernel 0: convert content -> fp16 plane; weights -> fp16 hi/lo planes
// ---------------------------------------------------------------------------
#define N4_A (8192 * 2048 / 4)
#define N4_W (1024 * 2048 / 4)

__global__ __launch_bounds__(256)
void cvt_split_all(const float4* __restrict__ content,
                   const float4* __restrict__ kw,
                   const float4* __restrict__ vw)
{
    int i = blockIdx.x * blockDim.x + threadIdx.x;
    const int total = N4_A + 2 * N4_W;
    const int stride = gridDim.x * blockDim.x;
    for (; i < total; i += stride) {
        if (i < N4_A) {
            float4 x = content[i];
            uint2 hv;
            asm("cvt.rn.f16x2.f32 %0, %2, %1;" : "=r"(hv.x) : "f"(x.x), "f"(x.y));
            asm("cvt.rn.f16x2.f32 %0, %2, %1;" : "=r"(hv.y) : "f"(x.z), "f"(x.w));
            reinterpret_cast<uint2*>(g_Af16)[i] = hv;
        } else {
            const float4* src;
            int j;
            uint2 *dhi, *dlo;
            if (i < N4_A + N4_W) {
                j = i - N4_A; src = kw;
                dhi = (uint2*)g_Bhi; dlo = (uint2*)g_Blo;
            } else {
                j = i - N4_A - N4_W; src = vw;
                dhi = (uint2*)(g_Bhi + 1024 * 2048);
                dlo = (uint2*)(g_Blo + 1024 * 2048);
            }
            float4 x = src[j];
            __half h0 = __float2half_rn(x.x), h1 = __float2half_rn(x.y);
            __half h2 = __float2half_rn(x.z), h3 = __float2half_rn(x.w);
            float l0 = x.x - __half2float(h0), l1 = x.y - __half2float(h1);
            float l2 = x.z - __half2float(h2), l3 = x.w - __half2float(h3);
            uint2 hv, lv;
            hv.x = (uint32_t)__half_as_ushort(h0) | ((uint32_t)__half_as_ushort(h1) << 16);
            hv.y = (uint32_t)__half_as_ushort(h2) | ((uint32_t)__half_as_ushort(h3) << 16);
            asm("cvt.rn.f16x2.f32 %0, %2, %1;" : "=r"(lv.x) : "f"(l0), "f"(l1));
            asm("cvt.rn.f16x2.f32 %0, %2, %1;" : "=r"(lv.y) : "f"(l2), "f"(l3));
            dhi[j] = hv;
            dlo[j] = lv;
        }
    }
}

// ---------------------------------------------------------------------------
// Kernel 1: GEMM, fp16 2-product scheme.
// CTA 128x128, K-chunk 16, 4-stage cp.async pipeline, one sync per chunk.
// Planes per stage: A(1), Bhi(1), Blo(1).
// ---------------------------------------------------------------------------
#define TM 128
#define TN 128
#define TK 16
#define NCH (DD / TK)        // 128
#define PITCH 48             // 32B data + 16B pad; conflict-free ldmatrix
#define PLANE (128 * PITCH)  // 6144
#define STAGE (3 * PLANE)    // 18432
#define NSTG 4
#define SMEMG (NSTG * STAGE) // 73728 -> 2 CTAs/SM

__device__ __forceinline__ void ldmx4(uint32_t* r, uint32_t addr) {
    asm volatile("ldmatrix.sync.aligned.m8n8.x4.shared.b16 {%0,%1,%2,%3}, [%4];"
                 : "=r"(r[0]), "=r"(r[1]), "=r"(r[2]), "=r"(r[3]) : "r"(addr));
}
__device__ __forceinline__ void mma16816(float* d, const uint32_t* a,
                                         uint32_t b0, uint32_t b1) {
    asm volatile(
        "mma.sync.aligned.m16n8k16.row.col.f32.f16.f16.f32 "
        "{%0,%1,%2,%3}, {%4,%5,%6,%7}, {%8,%9}, {%0,%1,%2,%3};"
        : "+f"(d[0]), "+f"(d[1]), "+f"(d[2]), "+f"(d[3])
        : "r"(a[0]), "r"(a[1]), "r"(a[2]), "r"(a[3]), "r"(b0), "r"(b1));
}
__device__ __forceinline__ void cpasync16(uint32_t dst, const void* src) {
    asm volatile("cp.async.cg.shared.global [%0], [%1], 16;"
                 :: "r"(dst), "l"(src) : "memory");
}

__global__ __launch_bounds__(256, 2)
void gemm_kv_mma(void)
{
    extern __shared__ char sm[];
    const uint32_t sb = smem_u32(sm);
    const int tid = threadIdx.x;
    const int wid = tid >> 5;
    const int lane = tid & 31;
    const int wm = wid >> 1;
    const int wn = wid & 1;

    const int m0 = blockIdx.y * TM;
    const int n0 = blockIdx.x * TN;

    const int crow = tid >> 1;
    const int q = tid & 1;
    const __half* srcA  = g_Af16 + (size_t)(m0 + crow) * DD + q * 8;
    const __half* srcBh = g_Bhi + (size_t)(n0 + crow) * DD + q * 8;
    const __half* srcBl = g_Blo + (size_t)(n0 + crow) * DD + q * 8;
    const uint32_t dbase = (uint32_t)(crow * PITCH + q * 16);

    float acc[2][8][4];
#pragma unroll
    for (int i = 0; i < 2; i++)
#pragma unroll
        for (int j = 0; j < 8; j++)
#pragma unroll
            for (int qq = 0; qq < 4; qq++) acc[i][j][qq] = 0.f;

    const uint32_t a_off =
        (uint32_t)((wm * 32 + (lane & 15)) * PITCH + ((lane & 16) ? 16 : 0));
    const uint32_t b_off =
        (uint32_t)((wn * 64 + (lane & 7) + ((lane & 16) ? 8 : 0)) * PITCH +
                   ((lane & 8) ? 16 : 0));

#define ISSUE_CHUNK(c)                                                          \
    do {                                                                        \
        const int k0_ = (c) * TK;                                               \
        const uint32_t st_ = sb + ((c) & (NSTG - 1)) * STAGE;                   \
        cpasync16(st_ + dbase,             srcA  + k0_);                        \
        cpasync16(st_ + PLANE + dbase,     srcBh + k0_);                        \
        cpasync16(st_ + 2 * PLANE + dbase, srcBl + k0_);                        \
        asm volatile("cp.async.commit_group;" ::: "memory");                    \
    } while (0)

    ISSUE_CHUNK(0);
    ISSUE_CHUNK(1);
    ISSUE_CHUNK(2);

    for (int c = 0; c < NCH; c++) {
        asm volatile("cp.async.wait_group 2;" ::: "memory");
        __syncthreads();
        const uint32_t st = sb + (c & (NSTG - 1)) * STAGE;

        uint32_t Af[2][4];
#pragma unroll
        for (int mt = 0; mt < 2; mt++)
            ldmx4(Af[mt], st + a_off + mt * 16 * PITCH);
#pragma unroll
        for (int np = 0; np < 4; np++) {
            uint32_t Bhi[4], Blo[4];
            ldmx4(Bhi, st + PLANE + b_off + np * 16 * PITCH);
            ldmx4(Blo, st + 2 * PLANE + b_off + np * 16 * PITCH);
            mma16816(acc[0][2 * np],     Af[0], Bhi[0], Bhi[1]);
            mma16816(acc[1][2 * np],     Af[1], Bhi[0], Bhi[1]);
            mma16816(acc[0][2 * np + 1], Af[0], Bhi[2], Bhi[3]);
            mma16816(acc[1][2 * np + 1], Af[1], Bhi[2], Bhi[3]);
            mma16816(acc[0][2 * np],     Af[0], Blo[0], Blo[1]);
            mma16816(acc[1][2 * np],     Af[1], Blo[0], Blo[1]);
            mma16816(acc[0][2 * np + 1], Af[0], Blo[2], Blo[3]);
            mma16816(acc[1][2 * np + 1], Af[1], Blo[2], Blo[3]);
        }

        if (c + 3 < NCH) {
            ISSUE_CHUNK(c + 3);
        } else {
            asm volatile("cp.async.commit_group;" ::: "memory");
        }
    }

    // epilogue
#pragma unroll
    for (int mt = 0; mt < 2; mt++) {
        const int row = m0 + wm * 32 + mt * 16 + (lane >> 2);
#pragma unroll
        for (int nt = 0; nt < 8; nt++) {
            const int col = n0 + wn * 64 + nt * 8 + 2 * (lane & 3);
            float* p0 = g_proj + (size_t)row * DD + col;
            float* p1 = g_proj + (size_t)(row + 8) * DD + col;
            *reinterpret_cast<float2*>(p0) = make_float2(acc[mt][nt][0], acc[mt][nt][1]);
            *reinterpret_cast<float2*>(p1) = make_float2(acc[mt][nt][2], acc[mt][nt][3]);
        }
    }
}

// ---------------------------------------------------------------------------
// Kernel 2: beta/gamma logits. 32 rows x 32 outputs per block, 2x2 blocking.
// ---------------------------------------------------------------------------
__global__ __launch_bounds__(256)
void proj_bg(const float* __restrict__ A,
             const float* __restrict__ b_w,
             const float* __restrict__ ts_w,
             const float* __restrict__ b_b,
             const float* __restrict__ ts_b)
{
    __shared__ float As[32][128];
    __shared__ float Ws[32][129];

    const int rb = blockIdx.x * 32;
    const int tid = threadIdx.x;
    const int r0 = (tid >> 4) * 2;
    const int j0 = (tid & 15) * 2;
    float a00 = 0.f, a01 = 0.f, a10 = 0.f, a11 = 0.f;

    for (int k0 = 0; k0 < DD; k0 += 128) {
        __syncthreads();
        for (int i = tid; i < 32 * 128; i += 256) {
            int row = i >> 7, col = i & 127;
            As[row][col] = A[(size_t)(rb + row) * DD + k0 + col];
            Ws[row][col] = (row < 16) ? b_w[(size_t)row * DD + k0 + col]
                                      : ts_w[(size_t)(row - 16) * DD + k0 + col];
        }
        __syncthreads();
#pragma unroll 4
        for (int d = 0; d < 128; d++) {
            float x0 = As[r0][d], x1 = As[r0 + 1][d];
            float w0 = Ws[j0][d], w1 = Ws[j0 + 1][d];
            a00 = fmaf(x0, w0, a00);
            a01 = fmaf(x0, w1, a01);
            a10 = fmaf(x1, w0, a10);
            a11 = fmaf(x1, w1, a11);
        }
    }

    float bias0 = (j0 < 16) ? b_b[j0] : ts_b[j0 - 16];
    float bias1 = (j0 + 1 < 16) ? b_b[j0 + 1] : ts_b[j0 + 1 - 16];
    g_bg[(size_t)(rb + r0) * 32 + j0]         = a00 + bias0;
    g_bg[(size_t)(rb + r0) * 32 + j0 + 1]     = a01 + bias1;
    g_bg[(size_t)(rb + r0 + 1) * 32 + j0]     = a10 + bias0;
    g_bg[(size_t)(rb + r0 + 1) * 32 + j0 + 1] = a11 + bias1;
}

// ---------------------------------------------------------------------------
// Kernel 3: recurrence (round-5 scalar version), 128 threads, lane pairs.
// ---------------------------------------------------------------------------
#define CH 32
#define KROW 72

__global__ __launch_bounds__(128)
void recurrent_update(const float* __restrict__ W_old,
                      const float* __restrict__ hd,
                      float* __restrict__ out)
{
    const int bh = blockIdx.x;
    const int b = bh >> 4;
    const int h = bh & 15;
    const int tid = threadIdx.x;
    const int v = tid >> 1;
    const int half = tid & 1;
    const int cb = half ? 36 : 0;

    __shared__ float ks[CH][KROW];
    __shared__ float vs[CH][DKK];
    __shared__ float betas[CH], gammas[CH], ninv[CH];

    float W[32];
    const float* wrow = W_old + ((size_t)bh * DKK + v) * DKK + half * 32;
#pragma unroll
    for (int d = 0; d < 32; d += 4) {
        float4 t = *reinterpret_cast<const float4*>(&wrow[d]);
        W[d] = t.x; W[d+1] = t.y; W[d+2] = t.z; W[d+3] = t.w;
    }
    const float hdl = hd[h];

    for (int t0 = 0; t0 < TT; t0 += CH) {
        __syncthreads();
        for (int i = tid; i < CH * DKK; i += 128) {
            int s = i >> 6, d = i & 63;
            int col = d + ((d >= 32) ? 4 : 0);
            size_t row = (size_t)(b * TT + t0 + s) * DD;
            ks[s][col] = g_proj[row + h * DKK + d];
            vs[s][d] = g_proj[row + 1024 + h * DKK + d];
        }
        __syncthreads();
        if (tid < CH) {
            int s = tid;
            float nsq = 0.f;
#pragma unroll
            for (int d = 0; d < 32; d++) {
                float x = ks[s][d], y = ks[s][36 + d];
                nsq = fmaf(x, x, nsq);
                nsq = fmaf(y, y, nsq);
            }
            ninv[s] = rsqrtf(fmaxf(nsq, 1e-24f));
            size_t brow = (size_t)(b * TT + t0 + s) * 32;
            betas[s] = 1.f / (1.f + expf(-g_bg[brow + h]));
            gammas[s] = 1.f / (1.f + expf(-(g_bg[brow + 16 + h] + hdl)));
        }
        __syncthreads();
        for (int i = tid; i < CH * DKK; i += 128) {
            int s = i >> 6, d = i & 63;
            int col = d + ((d >= 32) ? 4 : 0);
            ks[s][col] *= ninv[s];
        }
        __syncthreads();

        for (int s = 0; s < CH; s++) {
            float kr[32];
#pragma unroll
            for (int d = 0; d < 32; d += 4) {
                float4 t = *reinterpret_cast<const float4*>(&ks[s][cb + d]);
                kr[d] = t.x; kr[d+1] = t.y; kr[d+2] = t.z; kr[d+3] = t.w;
            }
            float a0 = 0.f, a1 = 0.f, a2 = 0.f, a3 = 0.f;
#pragma unroll
            for (int d = 0; d < 32; d += 4) {
                a0 = fmaf(W[d],     kr[d],     a0);
                a1 = fmaf(W[d + 1], kr[d + 1], a1);
                a2 = fmaf(W[d + 2], kr[d + 2], a2);
                a3 = fmaf(W[d + 3], kr[d + 3], a3);
            }
            float y = (a0 + a1) + (a2 + a3);
            y += __shfl_xor_sync(0xffffffffu, y, 1);
            float c = betas[s] * (vs[s][v] - y);
            float g = gammas[s];
#pragma unroll
            for (int d = 0; d < 32; d++)
                W[d] = fmaf(c, kr[d], g * W[d]);
        }
    }

    float* orow = out + ((size_t)bh * DKK + v) * DKK + half * 32;
#pragma unroll
    for (int d = 0; d < 32; d += 4) {
        float4 t = make_float4(W[d], W[d+1], W[d+2], W[d+3]);
        *reinterpret_cast<float4*>(&orow[d]) = t;
    }
}

// ---------------------------------------------------------------------------
extern "C" void kernel_launch(void* const* d_in, const int* in_sizes, int n_in,
                              void* d_out, int out_size)
{
    const float* W_old   = (const float*)d_in[0];
    const float* content = (const float*)d_in[1];
    const float* k_w     = (const float*)d_in[2];
    const float* v_w     = (const float*)d_in[3];
    const float* b_w     = (const float*)d_in[4];
    const float* b_b     = (const float*)d_in[5];
    const float* ts_w    = (const float*)d_in[6];
    const float* ts_b    = (const float*)d_in[7];
    const float* hd      = (const float*)d_in[8];
    float* out = (float*)d_out;

    cvt_split_all<<<4096, 256>>>((const float4*)content,
                                 (const float4*)k_w, (const float4*)v_w);

    cudaFuncSetAttribute(gemm_kv_mma, cudaFuncAttributeMaxDynamicSharedMemorySize,
                         SMEMG);
    dim3 g1(DD / TN, 8192 / TM);   // (16, 64)
    gemm_kv_mma<<<g1, 256, SMEMG>>>();
    proj_bg<<<256, 256>>>(content, b_w, ts_w, b_b, ts_b);
    recurrent_update<<<BB * HH, 128>>>(W_old, hd, out);
}

// round 8
// speedup vs baseline: 3.1544x; 1.0497x over previous
#include <cuda_runtime.h>
#include <cuda_bf16.h>
#include <cuda_fp16.h>
#include <math.h>
#include <stdint.h>

// Problem constants
#define BB 32
#define TT 256
#define DD 2048
#define HH 16
#define DKK 64

__device__ float g_proj[8192 * 2048];   // k|v projections (B*T, 2048)
__device__ float g_bg[8192 * 32];       // beta logits (0..15), gamma logits (16..31)

// fp16 operand planes
__device__ __half g_Af16[8192 * 2048];  // content, single fp16 plane
__device__ __half g_Bhi[2048 * 2048];   // weights hi; rows 0..1023 = k_w, 1024.. = v_w
__device__ __half g_Blo[2048 * 2048];   // weights residual

__device__ __forceinline__ uint32_t smem_u32(const void* p) {
    uint32_t a;
    asm("{ .reg .u64 t; cvta.to.shared.u64 t, %1; cvt.u32.u64 %0, t; }" : "=r"(a) : "l"(p));
    return a;
}

// ---------------------------------------------------------------------------
// Kernel 0: convert content -> fp16 plane; weights -> fp16 hi/lo planes
// ---------------------------------------------------------------------------
#define N4_A (8192 * 2048 / 4)
#define N4_W (1024 * 2048 / 4)

__global__ __launch_bounds__(256)
void cvt_split_all(const float4* __restrict__ content,
                   const float4* __restrict__ kw,
                   const float4* __restrict__ vw)
{
    int i = blockIdx.x * blockDim.x + threadIdx.x;
    const int total = N4_A + 2 * N4_W;
    const int stride = gridDim.x * blockDim.x;
    for (; i < total; i += stride) {
        if (i < N4_A) {
            float4 x = content[i];
            uint2 hv;
            asm("cvt.rn.f16x2.f32 %0, %2, %1;" : "=r"(hv.x) : "f"(x.x), "f"(x.y));
            asm("cvt.rn.f16x2.f32 %0, %2, %1;" : "=r"(hv.y) : "f"(x.z), "f"(x.w));
            reinterpret_cast<uint2*>(g_Af16)[i] = hv;
        } else {
            const float4* src;
            int j;
            uint2 *dhi, *dlo;
            if (i < N4_A + N4_W) {
                j = i - N4_A; src = kw;
                dhi = (uint2*)g_Bhi; dlo = (uint2*)g_Blo;
            } else {
                j = i - N4_A - N4_W; src = vw;
                dhi = (uint2*)(g_Bhi + 1024 * 2048);
                dlo = (uint2*)(g_Blo + 1024 * 2048);
            }
            float4 x = src[j];
            __half h0 = __float2half_rn(x.x), h1 = __float2half_rn(x.y);
            __half h2 = __float2half_rn(x.z), h3 = __float2half_rn(x.w);
            float l0 = x.x - __half2float(h0), l1 = x.y - __half2float(h1);
            float l2 = x.z - __half2float(h2), l3 = x.w - __half2float(h3);
            uint2 hv, lv;
            hv.x = (uint32_t)__half_as_ushort(h0) | ((uint32_t)__half_as_ushort(h1) << 16);
            hv.y = (uint32_t)__half_as_ushort(h2) | ((uint32_t)__half_as_ushort(h3) << 16);
            asm("cvt.rn.f16x2.f32 %0, %2, %1;" : "=r"(lv.x) : "f"(l0), "f"(l1));
            asm("cvt.rn.f16x2.f32 %0, %2, %1;" : "=r"(lv.y) : "f"(l2), "f"(l3));
            dhi[j] = hv;
            dlo[j] = lv;
        }
    }
}

// ---------------------------------------------------------------------------
// Kernel 1: GEMM, fp16 2-product scheme.
// CTA 128x128, K-chunk 16, 4-stage cp.async pipeline, one sync per chunk.
// Warp layout 2(M) x 4(N): warp tile 64x32 — minimizes smem fragment traffic.
// ---------------------------------------------------------------------------
#define TM 128
#define TN 128
#define TK 16
#define NCH (DD / TK)        // 128
#define PITCH 48             // 32B data + 16B pad; conflict-free ldmatrix
#define PLANE (128 * PITCH)  // 6144
#define STAGE (3 * PLANE)    // 18432
#define NSTG 4
#define SMEMG (NSTG * STAGE) // 73728 -> 2 CTAs/SM

__device__ __forceinline__ void ldmx4(uint32_t* r, uint32_t addr) {
    asm volatile("ldmatrix.sync.aligned.m8n8.x4.shared.b16 {%0,%1,%2,%3}, [%4];"
                 : "=r"(r[0]), "=r"(r[1]), "=r"(r[2]), "=r"(r[3]) : "r"(addr));
}
__device__ __forceinline__ void mma16816(float* d, const uint32_t* a,
                                         uint32_t b0, uint32_t b1) {
    asm volatile(
        "mma.sync.aligned.m16n8k16.row.col.f32.f16.f16.f32 "
        "{%0,%1,%2,%3}, {%4,%5,%6,%7}, {%8,%9}, {%0,%1,%2,%3};"
        : "+f"(d[0]), "+f"(d[1]), "+f"(d[2]), "+f"(d[3])
        : "r"(a[0]), "r"(a[1]), "r"(a[2]), "r"(a[3]), "r"(b0), "r"(b1));
}
__device__ __forceinline__ void cpasync16(uint32_t dst, const void* src) {
    asm volatile("cp.async.cg.shared.global [%0], [%1], 16;"
                 :: "r"(dst), "l"(src) : "memory");
}

__global__ __launch_bounds__(256, 2)
void gemm_kv_mma(void)
{
    extern __shared__ char sm[];
    const uint32_t sb = smem_u32(sm);
    const int tid = threadIdx.x;
    const int wid = tid >> 5;
    const int lane = tid & 31;
    const int wm = wid >> 2;           // 0..1 (64 rows each)
    const int wn = wid & 3;            // 0..3 (32 cols each)

    const int m0 = blockIdx.y * TM;
    const int n0 = blockIdx.x * TN;

    const int crow = tid >> 1;
    const int q = tid & 1;
    const __half* srcA  = g_Af16 + (size_t)(m0 + crow) * DD + q * 8;
    const __half* srcBh = g_Bhi + (size_t)(n0 + crow) * DD + q * 8;
    const __half* srcBl = g_Blo + (size_t)(n0 + crow) * DD + q * 8;
    const uint32_t dbase = (uint32_t)(crow * PITCH + q * 16);

    float acc[4][4][4];   // [mt][np*2+nb][4]
#pragma unroll
    for (int i = 0; i < 4; i++)
#pragma unroll
        for (int j = 0; j < 4; j++)
#pragma unroll
            for (int qq = 0; qq < 4; qq++) acc[i][j][qq] = 0.f;

    const uint32_t a_off =
        (uint32_t)((wm * 64 + (lane & 15)) * PITCH + ((lane & 16) ? 16 : 0));
    const uint32_t b_off =
        (uint32_t)((wn * 32 + (lane & 7) + ((lane & 16) ? 8 : 0)) * PITCH +
                   ((lane & 8) ? 16 : 0));

#define ISSUE_CHUNK(c)                                                          \
    do {                                                                        \
        const int k0_ = (c) * TK;                                               \
        const uint32_t st_ = sb + ((c) & (NSTG - 1)) * STAGE;                   \
        cpasync16(st_ + dbase,             srcA  + k0_);                        \
        cpasync16(st_ + PLANE + dbase,     srcBh + k0_);                        \
        cpasync16(st_ + 2 * PLANE + dbase, srcBl + k0_);                        \
        asm volatile("cp.async.commit_group;" ::: "memory");                    \
    } while (0)

    ISSUE_CHUNK(0);
    ISSUE_CHUNK(1);
    ISSUE_CHUNK(2);

    for (int c = 0; c < NCH; c++) {
        asm volatile("cp.async.wait_group 2;" ::: "memory");
        __syncthreads();
        const uint32_t st = sb + (c & (NSTG - 1)) * STAGE;

        uint32_t Af[4][4];
#pragma unroll
        for (int mt = 0; mt < 4; mt++)
            ldmx4(Af[mt], st + a_off + mt * 16 * PITCH);
#pragma unroll
        for (int np = 0; np < 2; np++) {
            uint32_t Bhi[4], Blo[4];
            ldmx4(Bhi, st + PLANE + b_off + np * 16 * PITCH);
            ldmx4(Blo, st + 2 * PLANE + b_off + np * 16 * PITCH);
            // hi products — 8 mma, distinct accs
#pragma unroll
            for (int mt = 0; mt < 4; mt++) {
                mma16816(acc[mt][2 * np],     Af[mt], Bhi[0], Bhi[1]);
                mma16816(acc[mt][2 * np + 1], Af[mt], Bhi[2], Bhi[3]);
            }
            // lo products — 8 mma, reuse distance 8
#pragma unroll
            for (int mt = 0; mt < 4; mt++) {
                mma16816(acc[mt][2 * np],     Af[mt], Blo[0], Blo[1]);
                mma16816(acc[mt][2 * np + 1], Af[mt], Blo[2], Blo[3]);
            }
        }

        if (c + 3 < NCH) {
            ISSUE_CHUNK(c + 3);
        } else {
            asm volatile("cp.async.commit_group;" ::: "memory");
        }
    }

    // epilogue
#pragma unroll
    for (int mt = 0; mt < 4; mt++) {
        const int row = m0 + wm * 64 + mt * 16 + (lane >> 2);
#pragma unroll
        for (int nt = 0; nt < 4; nt++) {
            const int col = n0 + wn * 32 + nt * 8 + 2 * (lane & 3);
            float* p0 = g_proj + (size_t)row * DD + col;
            float* p1 = g_proj + (size_t)(row + 8) * DD + col;
            *reinterpret_cast<float2*>(p0) = make_float2(acc[mt][nt][0], acc[mt][nt][1]);
            *reinterpret_cast<float2*>(p1) = make_float2(acc[mt][nt][2], acc[mt][nt][3]);
        }
    }
}

// ---------------------------------------------------------------------------
// Kernel 2: beta/gamma logits. 32 rows x 32 outputs per block, 2x2 blocking.
// ---------------------------------------------------------------------------
__global__ __launch_bounds__(256)
void proj_bg(const float* __restrict__ A,
             const float* __restrict__ b_w,
             const float* __restrict__ ts_w,
             const float* __restrict__ b_b,
             const float* __restrict__ ts_b)
{
    __shared__ float As[32][128];
    __shared__ float Ws[32][129];

    const int rb = blockIdx.x * 32;
    const int tid = threadIdx.x;
    const int r0 = (tid >> 4) * 2;
    const int j0 = (tid & 15) * 2;
    float a00 = 0.f, a01 = 0.f, a10 = 0.f, a11 = 0.f;

    for (int k0 = 0; k0 < DD; k0 += 128) {
        __syncthreads();
        for (int i = tid; i < 32 * 128; i += 256) {
            int row = i >> 7, col = i & 127;
            As[row][col] = A[(size_t)(rb + row) * DD + k0 + col];
            Ws[row][col] = (row < 16) ? b_w[(size_t)row * DD + k0 + col]
                                      : ts_w[(size_t)(row - 16) * DD + k0 + col];
        }
        __syncthreads();
#pragma unroll 4
        for (int d = 0; d < 128; d++) {
            float x0 = As[r0][d], x1 = As[r0 + 1][d];
            float w0 = Ws[j0][d], w1 = Ws[j0 + 1][d];
            a00 = fmaf(x0, w0, a00);
            a01 = fmaf(x0, w1, a01);
            a10 = fmaf(x1, w0, a10);
            a11 = fmaf(x1, w1, a11);
        }
    }

    float bias0 = (j0 < 16) ? b_b[j0] : ts_b[j0 - 16];
    float bias1 = (j0 + 1 < 16) ? b_b[j0 + 1] : ts_b[j0 + 1 - 16];
    g_bg[(size_t)(rb + r0) * 32 + j0]         = a00 + bias0;
    g_bg[(size_t)(rb + r0) * 32 + j0 + 1]     = a01 + bias1;
    g_bg[(size_t)(rb + r0 + 1) * 32 + j0]     = a10 + bias0;
    g_bg[(size_t)(rb + r0 + 1) * 32 + j0 + 1] = a11 + bias1;
}

// ---------------------------------------------------------------------------
// Kernel 3: recurrence, 128 threads, lane pairs split DK (32 cols each).
// ---------------------------------------------------------------------------
#define CH 32
#define KROW 72

__global__ __launch_bounds__(128)
void recurrent_update(const float* __restrict__ W_old,
                      const float* __restrict__ hd,
                      float* __restrict__ out)
{
    const int bh = blockIdx.x;
    const int b = bh >> 4;
    const int h = bh & 15;
    const int tid = threadIdx.x;
    const int v = tid >> 1;
    const int half = tid & 1;
    const int cb = half ? 36 : 0;

    __shared__ float ks[CH][KROW];
    __shared__ float vs[CH][DKK];
    __shared__ float betas[CH], gammas[CH], ninv[CH];

    float W[32];
    const float* wrow = W_old + ((size_t)bh * DKK + v) * DKK + half * 32;
#pragma unroll
    for (int d = 0; d < 32; d += 4) {
        float4 t = *reinterpret_cast<const float4*>(&wrow[d]);
        W[d] = t.x; W[d+1] = t.y; W[d+2] = t.z; W[d+3] = t.w;
    }
    const float hdl = hd[h];

    for (int t0 = 0; t0 < TT; t0 += CH) {
        __syncthreads();
        for (int i = tid; i < CH * DKK; i += 128) {
            int s = i >> 6, d = i & 63;
            int col = d + ((d >= 32) ? 4 : 0);
            size_t row = (size_t)(b * TT + t0 + s) * DD;
            ks[s][col] = g_proj[row + h * DKK + d];
            vs[s][d] = g_proj[row + 1024 + h * DKK + d];
        }
        __syncthreads();
        if (tid < CH) {
            int s = tid;
            float nsq = 0.f;
#pragma unroll
            for (int d = 0; d < 32; d++) {
                float x = ks[s][d], y = ks[s][36 + d];
                nsq = fmaf(x, x, nsq);
                nsq = fmaf(y, y, nsq);
            }
            ninv[s] = rsqrtf(fmaxf(nsq, 1e-24f));
            size_t brow = (size_t)(b * TT + t0 + s) * 32;
            betas[s] = 1.f / (1.f + expf(-g_bg[brow + h]));
            gammas[s] = 1.f / (1.f + expf(-(g_bg[brow + 16 + h] + hdl)));
        }
        __syncthreads();
        for (int i = tid; i < CH * DKK; i += 128) {
            int s = i >> 6, d = i & 63;
            int col = d + ((d >= 32) ? 4 : 0);
            ks[s][col] *= ninv[s];
        }
        __syncthreads();

        for (int s = 0; s < CH; s++) {
            float kr[32];
#pragma unroll
            for (int d = 0; d < 32; d += 4) {
                float4 t = *reinterpret_cast<const float4*>(&ks[s][cb + d]);
                kr[d] = t.x; kr[d+1] = t.y; kr[d+2] = t.z; kr[d+3] = t.w;
            }
            float a0 = 0.f, a1 = 0.f, a2 = 0.f, a3 = 0.f;
#pragma unroll
            for (int d = 0; d < 32; d += 4) {
                a0 = fmaf(W[d],     kr[d],     a0);
                a1 = fmaf(W[d + 1], kr[d + 1], a1);
                a2 = fmaf(W[d + 2], kr[d + 2], a2);
                a3 = fmaf(W[d + 3], kr[d + 3], a3);
            }
            float y = (a0 + a1) + (a2 + a3);
            y += __shfl_xor_sync(0xffffffffu, y, 1);
            float c = betas[s] * (vs[s][v] - y);
            float g = gammas[s];
#pragma unroll
            for (int d = 0; d < 32; d++)
                W[d] = fmaf(c, kr[d], g * W[d]);
        }
    }

    float* orow = out + ((size_t)bh * DKK + v) * DKK + half * 32;
#pragma unroll
    for (int d = 0; d < 32; d += 4) {
        float4 t = make_float4(W[d], W[d+1], W[d+2], W[d+3]);
        *reinterpret_cast<float4*>(&orow[d]) = t;
    }
}

// ---------------------------------------------------------------------------
extern "C" void kernel_launch(void* const* d_in, const int* in_sizes, int n_in,
                              void* d_out, int out_size)
{
    const float* W_old   = (const float*)d_in[0];
    const float* content = (const float*)d_in[1];
    const float* k_w     = (const float*)d_in[2];
    const float* v_w     = (const float*)d_in[3];
    const float* b_w     = (const float*)d_in[4];
    const float* b_b     = (const float*)d_in[5];
    const float* ts_w    = (const float*)d_in[6];
    const float* ts_b    = (const float*)d_in[7];
    const float* hd      = (const float*)d_in[8];
    float* out = (float*)d_out;

    cvt_split_all<<<4096, 256>>>((const float4*)content,
                                 (const float4*)k_w, (const float4*)v_w);

    cudaFuncSetAttribute(gemm_kv_mma, cudaFuncAttributeMaxDynamicSharedMemorySize,
                         SMEMG);
    dim3 g1(DD / TN, 8192 / TM);   // (16, 64)
    gemm_kv_mma<<<g1, 256, SMEMG>>>();
    proj_bg<<<256, 256>>>(content, b_w, ts_w, b_b, ts_b);
    recurrent_update<<<BB * HH, 128>>>(W_old, hd, out);
}

// round 9
// speedup vs baseline: 3.2001x; 1.0145x over previous
#include <cuda_runtime.h>
#include <cuda_bf16.h>
#include <cuda_fp16.h>
#include <math.h>
#include <stdint.h>

// Problem constants
#define BB 32
#define TT 256
#define DD 2048
#define HH 16
#define DKK 64

__device__ float g_proj[8192 * 2048];   // k|v projections (B*T, 2048)
__device__ float g_bg[8192 * 32];       // beta logits (0..15), gamma logits (16..31)

// fp16 operand planes
__device__ __half g_Af16[8192 * 2048];  // content, single fp16 plane
__device__ __half g_Bhi[2048 * 2048];   // weights hi; rows 0..1023 = k_w, 1024.. = v_w
__device__ __half g_Blo[2048 * 2048];   // weights residual

__device__ __forceinline__ uint32_t smem_u32(const void* p) {
    uint32_t a;
    asm("{ .reg .u64 t; cvta.to.shared.u64 t, %1; cvt.u32.u64 %0, t; }" : "=r"(a) : "l"(p));
    return a;
}

// ---------------------------------------------------------------------------
// Kernel 0: convert content -> fp16 plane; weights -> fp16 hi/lo planes
// ---------------------------------------------------------------------------
#define N4_A (8192 * 2048 / 4)
#define N4_W (1024 * 2048 / 4)

__global__ __launch_bounds__(256)
void cvt_split_all(const float4* __restrict__ content,
                   const float4* __restrict__ kw,
                   const float4* __restrict__ vw)
{
    int i = blockIdx.x * blockDim.x + threadIdx.x;
    const int total = N4_A + 2 * N4_W;
    const int stride = gridDim.x * blockDim.x;
    for (; i < total; i += stride) {
        if (i < N4_A) {
            float4 x = content[i];
            uint2 hv;
            asm("cvt.rn.f16x2.f32 %0, %2, %1;" : "=r"(hv.x) : "f"(x.x), "f"(x.y));
            asm("cvt.rn.f16x2.f32 %0, %2, %1;" : "=r"(hv.y) : "f"(x.z), "f"(x.w));
            reinterpret_cast<uint2*>(g_Af16)[i] = hv;
        } else {
            const float4* src;
            int j;
            uint2 *dhi, *dlo;
            if (i < N4_A + N4_W) {
                j = i - N4_A; src = kw;
                dhi = (uint2*)g_Bhi; dlo = (uint2*)g_Blo;
            } else {
                j = i - N4_A - N4_W; src = vw;
                dhi = (uint2*)(g_Bhi + 1024 * 2048);
                dlo = (uint2*)(g_Blo + 1024 * 2048);
            }
            float4 x = src[j];
            __half h0 = __float2half_rn(x.x), h1 = __float2half_rn(x.y);
            __half h2 = __float2half_rn(x.z), h3 = __float2half_rn(x.w);
            float l0 = x.x - __half2float(h0), l1 = x.y - __half2float(h1);
            float l2 = x.z - __half2float(h2), l3 = x.w - __half2float(h3);
            uint2 hv, lv;
            hv.x = (uint32_t)__half_as_ushort(h0) | ((uint32_t)__half_as_ushort(h1) << 16);
            hv.y = (uint32_t)__half_as_ushort(h2) | ((uint32_t)__half_as_ushort(h3) << 16);
            asm("cvt.rn.f16x2.f32 %0, %2, %1;" : "=r"(lv.x) : "f"(l0), "f"(l1));
            asm("cvt.rn.f16x2.f32 %0, %2, %1;" : "=r"(lv.y) : "f"(l2), "f"(l3));
            dhi[j] = hv;
            dlo[j] = lv;
        }
    }
}

// ---------------------------------------------------------------------------
// Kernel 1: GEMM, fp16 2-product scheme.
// CTA 128x128, K-chunk 16, 4-stage cp.async pipeline, one sync per chunk.
// Warp layout 2(M) x 4(N): warp tile 64x32.
// ---------------------------------------------------------------------------
#define TM 128
#define TN 128
#define TK 16
#define NCH (DD / TK)        // 128
#define PITCH 48
#define PLANE (128 * PITCH)  // 6144
#define STAGE (3 * PLANE)    // 18432
#define NSTG 4
#define SMEMG (NSTG * STAGE) // 73728 -> 2 CTAs/SM

__device__ __forceinline__ void ldmx4(uint32_t* r, uint32_t addr) {
    asm volatile("ldmatrix.sync.aligned.m8n8.x4.shared.b16 {%0,%1,%2,%3}, [%4];"
                 : "=r"(r[0]), "=r"(r[1]), "=r"(r[2]), "=r"(r[3]) : "r"(addr));
}
__device__ __forceinline__ void mma16816(float* d, const uint32_t* a,
                                         uint32_t b0, uint32_t b1) {
    asm volatile(
        "mma.sync.aligned.m16n8k16.row.col.f32.f16.f16.f32 "
        "{%0,%1,%2,%3}, {%4,%5,%6,%7}, {%8,%9}, {%0,%1,%2,%3};"
        : "+f"(d[0]), "+f"(d[1]), "+f"(d[2]), "+f"(d[3])
        : "r"(a[0]), "r"(a[1]), "r"(a[2]), "r"(a[3]), "r"(b0), "r"(b1));
}
__device__ __forceinline__ void cpasync16(uint32_t dst, const void* src) {
    asm volatile("cp.async.cg.shared.global [%0], [%1], 16;"
                 :: "r"(dst), "l"(src) : "memory");
}

__global__ __launch_bounds__(256, 2)
void gemm_kv_mma(void)
{
    extern __shared__ char sm[];
    const uint32_t sb = smem_u32(sm);
    const int tid = threadIdx.x;
    const int wid = tid >> 5;
    const int lane = tid & 31;
    const int wm = wid >> 2;
    const int wn = wid & 3;

    const int m0 = blockIdx.y * TM;
    const int n0 = blockIdx.x * TN;

    const int crow = tid >> 1;
    const int q = tid & 1;
    const __half* srcA  = g_Af16 + (size_t)(m0 + crow) * DD + q * 8;
    const __half* srcBh = g_Bhi + (size_t)(n0 + crow) * DD + q * 8;
    const __half* srcBl = g_Blo + (size_t)(n0 + crow) * DD + q * 8;
    const uint32_t dbase = (uint32_t)(crow * PITCH + q * 16);

    float acc[4][4][4];
#pragma unroll
    for (int i = 0; i < 4; i++)
#pragma unroll
        for (int j = 0; j < 4; j++)
#pragma unroll
            for (int qq = 0; qq < 4; qq++) acc[i][j][qq] = 0.f;

    const uint32_t a_off =
        (uint32_t)((wm * 64 + (lane & 15)) * PITCH + ((lane & 16) ? 16 : 0));
    const uint32_t b_off =
        (uint32_t)((wn * 32 + (lane & 7) + ((lane & 16) ? 8 : 0)) * PITCH +
                   ((lane & 8) ? 16 : 0));

#define ISSUE_CHUNK(c)                                                          \
    do {                                                                        \
        const int k0_ = (c) * TK;                                               \
        const uint32_t st_ = sb + ((c) & (NSTG - 1)) * STAGE;                   \
        cpasync16(st_ + dbase,             srcA  + k0_);                        \
        cpasync16(st_ + PLANE + dbase,     srcBh + k0_);                        \
        cpasync16(st_ + 2 * PLANE + dbase, srcBl + k0_);                        \
        asm volatile("cp.async.commit_group;" ::: "memory");                    \
    } while (0)

    ISSUE_CHUNK(0);
    ISSUE_CHUNK(1);
    ISSUE_CHUNK(2);

    for (int c = 0; c < NCH; c++) {
        asm volatile("cp.async.wait_group 2;" ::: "memory");
        __syncthreads();
        const uint32_t st = sb + (c & (NSTG - 1)) * STAGE;

        uint32_t Af[4][4];
#pragma unroll
        for (int mt = 0; mt < 4; mt++)
            ldmx4(Af[mt], st + a_off + mt * 16 * PITCH);
#pragma unroll
        for (int np = 0; np < 2; np++) {
            uint32_t Bhi[4], Blo[4];
            ldmx4(Bhi, st + PLANE + b_off + np * 16 * PITCH);
            ldmx4(Blo, st + 2 * PLANE + b_off + np * 16 * PITCH);
#pragma unroll
            for (int mt = 0; mt < 4; mt++) {
                mma16816(acc[mt][2 * np],     Af[mt], Bhi[0], Bhi[1]);
                mma16816(acc[mt][2 * np + 1], Af[mt], Bhi[2], Bhi[3]);
            }
#pragma unroll
            for (int mt = 0; mt < 4; mt++) {
                mma16816(acc[mt][2 * np],     Af[mt], Blo[0], Blo[1]);
                mma16816(acc[mt][2 * np + 1], Af[mt], Blo[2], Blo[3]);
            }
        }

        if (c + 3 < NCH) {
            ISSUE_CHUNK(c + 3);
        } else {
            asm volatile("cp.async.commit_group;" ::: "memory");
        }
    }

    // epilogue
#pragma unroll
    for (int mt = 0; mt < 4; mt++) {
        const int row = m0 + wm * 64 + mt * 16 + (lane >> 2);
#pragma unroll
        for (int nt = 0; nt < 4; nt++) {
            const int col = n0 + wn * 32 + nt * 8 + 2 * (lane & 3);
            float* p0 = g_proj + (size_t)row * DD + col;
            float* p1 = g_proj + (size_t)(row + 8) * DD + col;
            *reinterpret_cast<float2*>(p0) = make_float2(acc[mt][nt][0], acc[mt][nt][1]);
            *reinterpret_cast<float2*>(p1) = make_float2(acc[mt][nt][2], acc[mt][nt][3]);
        }
    }
}

// ---------------------------------------------------------------------------
// Kernel 2: beta/gamma logits. 32 rows x 32 outputs per block, 2x2 blocking.
// ---------------------------------------------------------------------------
__global__ __launch_bounds__(256)
void proj_bg(const float* __restrict__ A,
             const float* __restrict__ b_w,
             const float* __restrict__ ts_w,
             const float* __restrict__ b_b,
             const float* __restrict__ ts_b)
{
    __shared__ float As[32][128];
    __shared__ float Ws[32][129];

    const int rb = blockIdx.x * 32;
    const int tid = threadIdx.x;
    const int r0 = (tid >> 4) * 2;
    const int j0 = (tid & 15) * 2;
    float a00 = 0.f, a01 = 0.f, a10 = 0.f, a11 = 0.f;

    for (int k0 = 0; k0 < DD; k0 += 128) {
        __syncthreads();
        for (int i = tid; i < 32 * 128; i += 256) {
            int row = i >> 7, col = i & 127;
            As[row][col] = A[(size_t)(rb + row) * DD + k0 + col];
            Ws[row][col] = (row < 16) ? b_w[(size_t)row * DD + k0 + col]
                                      : ts_w[(size_t)(row - 16) * DD + k0 + col];
        }
        __syncthreads();
#pragma unroll 4
        for (int d = 0; d < 128; d++) {
            float x0 = As[r0][d], x1 = As[r0 + 1][d];
            float w0 = Ws[j0][d], w1 = Ws[j0 + 1][d];
            a00 = fmaf(x0, w0, a00);
            a01 = fmaf(x0, w1, a01);
            a10 = fmaf(x1, w0, a10);
            a11 = fmaf(x1, w1, a11);
        }
    }

    float bias0 = (j0 < 16) ? b_b[j0] : ts_b[j0 - 16];
    float bias1 = (j0 + 1 < 16) ? b_b[j0 + 1] : ts_b[j0 + 1 - 16];
    g_bg[(size_t)(rb + r0) * 32 + j0]         = a00 + bias0;
    g_bg[(size_t)(rb + r0) * 32 + j0 + 1]     = a01 + bias1;
    g_bg[(size_t)(rb + r0 + 1) * 32 + j0]     = a10 + bias0;
    g_bg[(size_t)(rb + r0 + 1) * 32 + j0 + 1] = a11 + bias1;
}

// ---------------------------------------------------------------------------
// Kernel 3: recurrence with gamma factored out (W = S*U), renorm every 16.
// 128 threads, lane pairs split DK (32 cols each).
// ---------------------------------------------------------------------------
#define CH 32
#define KROW 72

__global__ __launch_bounds__(128)
void recurrent_update(const float* __restrict__ W_old,
                      const float* __restrict__ hd,
                      float* __restrict__ out)
{
    const int bh = blockIdx.x;
    const int b = bh >> 4;
    const int h = bh & 15;
    const int tid = threadIdx.x;
    const int v = tid >> 1;
    const int half = tid & 1;
    const int cb = half ? 36 : 0;

    __shared__ float ks[CH][KROW];
    __shared__ float vs[CH][DKK];
    __shared__ float betas[CH], gammas[CH], ginv[CH], ninv[CH];

    float U[32];   // scaled state: W = S * U  (S == 1 at chunk boundaries)
    const float* wrow = W_old + ((size_t)bh * DKK + v) * DKK + half * 32;
#pragma unroll
    for (int d = 0; d < 32; d += 4) {
        float4 t = *reinterpret_cast<const float4*>(&wrow[d]);
        U[d] = t.x; U[d+1] = t.y; U[d+2] = t.z; U[d+3] = t.w;
    }
    const float hdl = hd[h];

    for (int t0 = 0; t0 < TT; t0 += CH) {
        __syncthreads();
        for (int i = tid; i < CH * DKK; i += 128) {
            int s = i >> 6, d = i & 63;
            int col = d + ((d >= 32) ? 4 : 0);
            size_t row = (size_t)(b * TT + t0 + s) * DD;
            ks[s][col] = g_proj[row + h * DKK + d];
            vs[s][d] = g_proj[row + 1024 + h * DKK + d];
        }
        __syncthreads();
        if (tid < CH) {
            int s = tid;
            float nsq = 0.f;
#pragma unroll
            for (int d = 0; d < 32; d++) {
                float x = ks[s][d], y = ks[s][36 + d];
                nsq = fmaf(x, x, nsq);
                nsq = fmaf(y, y, nsq);
            }
            ninv[s] = rsqrtf(fmaxf(nsq, 1e-24f));
            size_t brow = (size_t)(b * TT + t0 + s) * 32;
            betas[s] = 1.f / (1.f + expf(-g_bg[brow + h]));
            float gm = 1.f / (1.f + expf(-(g_bg[brow + 16 + h] + hdl)));
            gammas[s] = gm;
            ginv[s] = 1.f / gm;
        }
        __syncthreads();
        for (int i = tid; i < CH * DKK; i += 128) {
            int s = i >> 6, d = i & 63;
            int col = d + ((d >= 32) ? 4 : 0);
            ks[s][col] *= ninv[s];
        }
        __syncthreads();

#pragma unroll
        for (int hcb = 0; hcb < CH; hcb += 16) {
            float S = 1.f, invS = 1.f;
            for (int s = hcb; s < hcb + 16; s++) {
                S *= gammas[s];
                invS *= ginv[s];
                float kr[32];
#pragma unroll
                for (int d = 0; d < 32; d += 4) {
                    float4 t = *reinterpret_cast<const float4*>(&ks[s][cb + d]);
                    kr[d] = t.x; kr[d+1] = t.y; kr[d+2] = t.z; kr[d+3] = t.w;
                }
                float a0 = 0.f, a1 = 0.f, a2 = 0.f, a3 = 0.f;
#pragma unroll
                for (int d = 0; d < 32; d += 4) {
                    a0 = fmaf(U[d],     kr[d],     a0);
                    a1 = fmaf(U[d + 1], kr[d + 1], a1);
                    a2 = fmaf(U[d + 2], kr[d + 2], a2);
                    a3 = fmaf(U[d + 3], kr[d + 3], a3);
                }
                float y = (a0 + a1) + (a2 + a3);
                y += __shfl_xor_sync(0xffffffffu, y, 1);
                // actual y_prev = S_{t-1} * (U·k); here S already includes γ_t,
                // so y_prev = (S * ginv[s]) * y; fold: c = β(v − S·ginv·y)
                float yprev = S * ginv[s] * y;
                float c2 = betas[s] * (vs[s][v] - yprev) * invS;
#pragma unroll
                for (int d = 0; d < 32; d++)
                    U[d] = fmaf(c2, kr[d], U[d]);
            }
            // renorm: fold S back into U
#pragma unroll
            for (int d = 0; d < 32; d++)
                U[d] *= S;
        }
    }

    float* orow = out + ((size_t)bh * DKK + v) * DKK + half * 32;
#pragma unroll
    for (int d = 0; d < 32; d += 4) {
        float4 t = make_float4(U[d], U[d+1], U[d+2], U[d+3]);
        *reinterpret_cast<float4*>(&orow[d]) = t;
    }
}

// ---------------------------------------------------------------------------
extern "C" void kernel_launch(void* const* d_in, const int* in_sizes, int n_in,
                              void* d_out, int out_size)
{
    const float* W_old   = (const float*)d_in[0];
    const float* content = (const float*)d_in[1];
    const float* k_w     = (const float*)d_in[2];
    const float* v_w     = (const float*)d_in[3];
    const float* b_w     = (const float*)d_in[4];
    const float* b_b     = (const float*)d_in[5];
    const float* ts_w    = (const float*)d_in[6];
    const float* ts_b    = (const float*)d_in[7];
    const float* hd      = (const float*)d_in[8];
    float* out = (float*)d_out;

    cvt_split_all<<<4096, 256>>>((const float4*)content,
                                 (const float4*)k_w, (const float4*)v_w);

    cudaFuncSetAttribute(gemm_kv_mma, cudaFuncAttributeMaxDynamicSharedMemorySize,
                         SMEMG);
    dim3 g1(DD / TN, 8192 / TM);   // (16, 64)
    gemm_kv_mma<<<g1, 256, SMEMG>>>();
    proj_bg<<<256, 256>>>(content, b_w, ts_w, b_b, ts_b);
    recurrent_update<<<BB * HH, 128>>>(W_old, hd, out);
}

// round 10
// speedup vs baseline: 4.0661x; 1.2706x over previous
#include <cuda_runtime.h>
#include <cuda_bf16.h>
#include <cuda_fp16.h>
#include <math.h>
#include <stdint.h>

// Problem constants
#define BB 32
#define TT 256
#define DD 2048
#define HH 16
#define DKK 64

__device__ float g_proj[8192 * 2048];   // k|v projections (B*T, 2048)
__device__ float g_bg[8192 * 32];       // beta logits (0..15), gamma logits (16..31)

// fp16 operand planes (single product: C = A_f16 * B_f16)
__device__ __half g_Af16[8192 * 2048];  // content
__device__ __half g_Bf16[2048 * 2048];  // weights; rows 0..1023 = k_w, 1024.. = v_w

__device__ __forceinline__ uint32_t smem_u32(const void* p) {
    uint32_t a;
    asm("{ .reg .u64 t; cvta.to.shared.u64 t, %1; cvt.u32.u64 %0, t; }" : "=r"(a) : "l"(p));
    return a;
}

// ---------------------------------------------------------------------------
// Kernel 0: convert content + weights to fp16 planes
// ---------------------------------------------------------------------------
#define N4_A (8192 * 2048 / 4)
#define N4_W (1024 * 2048 / 4)

__global__ __launch_bounds__(256)
void cvt_all(const float4* __restrict__ content,
             const float4* __restrict__ kw,
             const float4* __restrict__ vw)
{
    int i = blockIdx.x * blockDim.x + threadIdx.x;
    const int total = N4_A + 2 * N4_W;
    const int stride = gridDim.x * blockDim.x;
    for (; i < total; i += stride) {
        const float4* src;
        uint2* dst;
        int j;
        if (i < N4_A) {
            j = i; src = content; dst = (uint2*)g_Af16;
        } else if (i < N4_A + N4_W) {
            j = i - N4_A; src = kw; dst = (uint2*)g_Bf16;
        } else {
            j = i - N4_A - N4_W; src = vw; dst = (uint2*)(g_Bf16 + 1024 * 2048);
        }
        float4 x = src[j];
        uint2 hv;
        asm("cvt.rn.f16x2.f32 %0, %2, %1;" : "=r"(hv.x) : "f"(x.x), "f"(x.y));
        asm("cvt.rn.f16x2.f32 %0, %2, %1;" : "=r"(hv.y) : "f"(x.z), "f"(x.w));
        dst[j] = hv;
    }
}

// ---------------------------------------------------------------------------
// Kernel 1: GEMM, single-product fp16.
// CTA 128x128, K-chunk 16, 4-stage cp.async pipeline, one sync per chunk.
// Warp layout 2(M) x 4(N): warp tile 64x32.
// ---------------------------------------------------------------------------
#define TM 128
#define TN 128
#define TK 16
#define NCH (DD / TK)        // 128
#define PITCH 48
#define PLANE (128 * PITCH)  // 6144
#define STAGE (2 * PLANE)    // 12288
#define NSTG 4
#define SMEMG (NSTG * STAGE) // 49152 -> 2 CTAs/SM easily

__device__ __forceinline__ void ldmx4(uint32_t* r, uint32_t addr) {
    asm volatile("ldmatrix.sync.aligned.m8n8.x4.shared.b16 {%0,%1,%2,%3}, [%4];"
                 : "=r"(r[0]), "=r"(r[1]), "=r"(r[2]), "=r"(r[3]) : "r"(addr));
}
__device__ __forceinline__ void mma16816(float* d, const uint32_t* a,
                                         uint32_t b0, uint32_t b1) {
    asm volatile(
        "mma.sync.aligned.m16n8k16.row.col.f32.f16.f16.f32 "
        "{%0,%1,%2,%3}, {%4,%5,%6,%7}, {%8,%9}, {%0,%1,%2,%3};"
        : "+f"(d[0]), "+f"(d[1]), "+f"(d[2]), "+f"(d[3])
        : "r"(a[0]), "r"(a[1]), "r"(a[2]), "r"(a[3]), "r"(b0), "r"(b1));
}
__device__ __forceinline__ void cpasync16(uint32_t dst, const void* src) {
    asm volatile("cp.async.cg.shared.global [%0], [%1], 16;"
                 :: "r"(dst), "l"(src) : "memory");
}

__global__ __launch_bounds__(256, 2)
void gemm_kv_mma(void)
{
    extern __shared__ char sm[];
    const uint32_t sb = smem_u32(sm);
    const int tid = threadIdx.x;
    const int wid = tid >> 5;
    const int lane = tid & 31;
    const int wm = wid >> 2;
    const int wn = wid & 3;

    const int m0 = blockIdx.y * TM;
    const int n0 = blockIdx.x * TN;

    const int crow = tid >> 1;
    const int q = tid & 1;
    const __half* srcA = g_Af16 + (size_t)(m0 + crow) * DD + q * 8;
    const __half* srcB = g_Bf16 + (size_t)(n0 + crow) * DD + q * 8;
    const uint32_t dbase = (uint32_t)(crow * PITCH + q * 16);

    float acc[4][4][4];
#pragma unroll
    for (int i = 0; i < 4; i++)
#pragma unroll
        for (int j = 0; j < 4; j++)
#pragma unroll
            for (int qq = 0; qq < 4; qq++) acc[i][j][qq] = 0.f;

    const uint32_t a_off =
        (uint32_t)((wm * 64 + (lane & 15)) * PITCH + ((lane & 16) ? 16 : 0));
    const uint32_t b_off =
        (uint32_t)((wn * 32 + (lane & 7) + ((lane & 16) ? 8 : 0)) * PITCH +
                   ((lane & 8) ? 16 : 0));

#define ISSUE_CHUNK(c)                                                          \
    do {                                                                        \
        const int k0_ = (c) * TK;                                               \
        const uint32_t st_ = sb + ((c) & (NSTG - 1)) * STAGE;                   \
        cpasync16(st_ + dbase,         srcA + k0_);                             \
        cpasync16(st_ + PLANE + dbase, srcB + k0_);                             \
        asm volatile("cp.async.commit_group;" ::: "memory");                    \
    } while (0)

    ISSUE_CHUNK(0);
    ISSUE_CHUNK(1);
    ISSUE_CHUNK(2);

    for (int c = 0; c < NCH; c++) {
        asm volatile("cp.async.wait_group 2;" ::: "memory");
        __syncthreads();
        const uint32_t st = sb + (c & (NSTG - 1)) * STAGE;

        uint32_t Af[4][4];
#pragma unroll
        for (int mt = 0; mt < 4; mt++)
            ldmx4(Af[mt], st + a_off + mt * 16 * PITCH);
#pragma unroll
        for (int np = 0; np < 2; np++) {
            uint32_t Bf[4];
            ldmx4(Bf, st + PLANE + b_off + np * 16 * PITCH);
#pragma unroll
            for (int mt = 0; mt < 4; mt++) {
                mma16816(acc[mt][2 * np],     Af[mt], Bf[0], Bf[1]);
                mma16816(acc[mt][2 * np + 1], Af[mt], Bf[2], Bf[3]);
            }
        }

        if (c + 3 < NCH) {
            ISSUE_CHUNK(c + 3);
        } else {
            asm volatile("cp.async.commit_group;" ::: "memory");
        }
    }

    // epilogue
#pragma unroll
    for (int mt = 0; mt < 4; mt++) {
        const int row = m0 + wm * 64 + mt * 16 + (lane >> 2);
#pragma unroll
        for (int nt = 0; nt < 4; nt++) {
            const int col = n0 + wn * 32 + nt * 8 + 2 * (lane & 3);
            float* p0 = g_proj + (size_t)row * DD + col;
            float* p1 = g_proj + (size_t)(row + 8) * DD + col;
            *reinterpret_cast<float2*>(p0) = make_float2(acc[mt][nt][0], acc[mt][nt][1]);
            *reinterpret_cast<float2*>(p1) = make_float2(acc[mt][nt][2], acc[mt][nt][3]);
        }
    }
}

// ---------------------------------------------------------------------------
// Kernel 2: beta/gamma logits. 32 rows x 32 outputs per block, 2x2 blocking.
// ---------------------------------------------------------------------------
__global__ __launch_bounds__(256)
void proj_bg(const float* __restrict__ A,
             const float* __restrict__ b_w,
             const float* __restrict__ ts_w,
             const float* __restrict__ b_b,
             const float* __restrict__ ts_b)
{
    __shared__ float As[32][128];
    __shared__ float Ws[32][129];

    const int rb = blockIdx.x * 32;
    const int tid = threadIdx.x;
    const int r0 = (tid >> 4) * 2;
    const int j0 = (tid & 15) * 2;
    float a00 = 0.f, a01 = 0.f, a10 = 0.f, a11 = 0.f;

    for (int k0 = 0; k0 < DD; k0 += 128) {
        __syncthreads();
        for (int i = tid; i < 32 * 128; i += 256) {
            int row = i >> 7, col = i & 127;
            As[row][col] = A[(size_t)(rb + row) * DD + k0 + col];
            Ws[row][col] = (row < 16) ? b_w[(size_t)row * DD + k0 + col]
                                      : ts_w[(size_t)(row - 16) * DD + k0 + col];
        }
        __syncthreads();
#pragma unroll 4
        for (int d = 0; d < 128; d++) {
            float x0 = As[r0][d], x1 = As[r0 + 1][d];
            float w0 = Ws[j0][d], w1 = Ws[j0 + 1][d];
            a00 = fmaf(x0, w0, a00);
            a01 = fmaf(x0, w1, a01);
            a10 = fmaf(x1, w0, a10);
            a11 = fmaf(x1, w1, a11);
        }
    }

    float bias0 = (j0 < 16) ? b_b[j0] : ts_b[j0 - 16];
    float bias1 = (j0 + 1 < 16) ? b_b[j0 + 1] : ts_b[j0 + 1 - 16];
    g_bg[(size_t)(rb + r0) * 32 + j0]         = a00 + bias0;
    g_bg[(size_t)(rb + r0) * 32 + j0 + 1]     = a01 + bias1;
    g_bg[(size_t)(rb + r0 + 1) * 32 + j0]     = a10 + bias0;
    g_bg[(size_t)(rb + r0 + 1) * 32 + j0 + 1] = a11 + bias1;
}

// ---------------------------------------------------------------------------
// Kernel 3: recurrence with gamma factored out (W = S*U), renorm every 16.
// 128 threads, lane pairs split DK (32 cols each).
// ---------------------------------------------------------------------------
#define CH 32
#define KROW 72

__global__ __launch_bounds__(128)
void recurrent_update(const float* __restrict__ W_old,
                      const float* __restrict__ hd,
                      float* __restrict__ out)
{
    const int bh = blockIdx.x;
    const int b = bh >> 4;
    const int h = bh & 15;
    const int tid = threadIdx.x;
    const int v = tid >> 1;
    const int half = tid & 1;
    const int cb = half ? 36 : 0;

    __shared__ float ks[CH][KROW];
    __shared__ float vs[CH][DKK];
    __shared__ float betas[CH], gammas[CH], ginv[CH], ninv[CH];

    float U[32];
    const float* wrow = W_old + ((size_t)bh * DKK + v) * DKK + half * 32;
#pragma unroll
    for (int d = 0; d < 32; d += 4) {
        float4 t = *reinterpret_cast<const float4*>(&wrow[d]);
        U[d] = t.x; U[d+1] = t.y; U[d+2] = t.z; U[d+3] = t.w;
    }
    const float hdl = hd[h];

    for (int t0 = 0; t0 < TT; t0 += CH) {
        __syncthreads();
        for (int i = tid; i < CH * DKK; i += 128) {
            int s = i >> 6, d = i & 63;
            int col = d + ((d >= 32) ? 4 : 0);
            size_t row = (size_t)(b * TT + t0 + s) * DD;
            ks[s][col] = g_proj[row + h * DKK + d];
            vs[s][d] = g_proj[row + 1024 + h * DKK + d];
        }
        __syncthreads();
        if (tid < CH) {
            int s = tid;
            float nsq = 0.f;
#pragma unroll
            for (int d = 0; d < 32; d++) {
                float x = ks[s][d], y = ks[s][36 + d];
                nsq = fmaf(x, x, nsq);
                nsq = fmaf(y, y, nsq);
            }
            ninv[s] = rsqrtf(fmaxf(nsq, 1e-24f));
            size_t brow = (size_t)(b * TT + t0 + s) * 32;
            betas[s] = 1.f / (1.f + expf(-g_bg[brow + h]));
            float gm = 1.f / (1.f + expf(-(g_bg[brow + 16 + h] + hdl)));
            gammas[s] = gm;
            ginv[s] = 1.f / gm;
        }
        __syncthreads();
        for (int i = tid; i < CH * DKK; i += 128) {
            int s = i >> 6, d = i & 63;
            int col = d + ((d >= 32) ? 4 : 0);
            ks[s][col] *= ninv[s];
        }
        __syncthreads();

#pragma unroll
        for (int hcb = 0; hcb < CH; hcb += 16) {
            float S = 1.f, invS = 1.f;
            for (int s = hcb; s < hcb + 16; s++) {
                S *= gammas[s];
                invS *= ginv[s];
                float kr[32];
#pragma unroll
                for (int d = 0; d < 32; d += 4) {
                    float4 t = *reinterpret_cast<const float4*>(&ks[s][cb + d]);
                    kr[d] = t.x; kr[d+1] = t.y; kr[d+2] = t.z; kr[d+3] = t.w;
                }
                float a0 = 0.f, a1 = 0.f, a2 = 0.f, a3 = 0.f;
#pragma unroll
                for (int d = 0; d < 32; d += 4) {
                    a0 = fmaf(U[d],     kr[d],     a0);
                    a1 = fmaf(U[d + 1], kr[d + 1], a1);
                    a2 = fmaf(U[d + 2], kr[d + 2], a2);
                    a3 = fmaf(U[d + 3], kr[d + 3], a3);
                }
                float y = (a0 + a1) + (a2 + a3);
                y += __shfl_xor_sync(0xffffffffu, y, 1);
                float yprev = S * ginv[s] * y;
                float c2 = betas[s] * (vs[s][v] - yprev) * invS;
#pragma unroll
                for (int d = 0; d < 32; d++)
                    U[d] = fmaf(c2, kr[d], U[d]);
            }
#pragma unroll
            for (int d = 0; d < 32; d++)
                U[d] *= S;
        }
    }

    float* orow = out + ((size_t)bh * DKK + v) * DKK + half * 32;
#pragma unroll
    for (int d = 0; d < 32; d += 4) {
        float4 t = make_float4(U[d], U[d+1], U[d+2], U[d+3]);
        *reinterpret_cast<float4*>(&orow[d]) = t;
    }
}

// ---------------------------------------------------------------------------
extern "C" void kernel_launch(void* const* d_in, const int* in_sizes, int n_in,
                              void* d_out, int out_size)
{
    const float* W_old   = (const float*)d_in[0];
    const float* content = (const float*)d_in[1];
    const float* k_w     = (const float*)d_in[2];
    const float* v_w     = (const float*)d_in[3];
    const float* b_w     = (const float*)d_in[4];
    const float* b_b     = (const float*)d_in[5];
    const float* ts_w    = (const float*)d_in[6];
    const float* ts_b    = (const float*)d_in[7];
    const float* hd      = (const float*)d_in[8];
    float* out = (float*)d_out;

    cvt_all<<<4096, 256>>>((const float4*)content,
                           (const float4*)k_w, (const float4*)v_w);

    cudaFuncSetAttribute(gemm_kv_mma, cudaFuncAttributeMaxDynamicSharedMemorySize,
                         SMEMG);
    dim3 g1(DD / TN, 8192 / TM);   // (16, 64)
    gemm_kv_mma<<<g1, 256, SMEMG>>>();
    proj_bg<<<256, 256>>>(content, b_w, ts_w, b_b, ts_b);
    recurrent_update<<<BB * HH, 128>>>(W_old, hd, out);
}

// round 11
// speedup vs baseline: 4.2852x; 1.0539x over previous
#include <cuda_runtime.h>
#include <cuda_bf16.h>
#include <cuda_fp16.h>
#include <math.h>
#include <stdint.h>

// Problem constants
#define BB 32
#define TT 256
#define DD 2048
#define HH 16
#define DKK 64

__device__ float g_proj[8192 * 2048];   // k|v projections (B*T, 2048)
__device__ float g_bg[8192 * 32];       // beta logits (0..15), gamma logits (16..31)

// fp16 operand planes (single product: C = A_f16 * B_f16)
__device__ __half g_Af16[8192 * 2048];  // content (written by proj_bg)
__device__ __half g_Bf16[2048 * 2048];  // weights; rows 0..1023 = k_w, 1024.. = v_w

__device__ __forceinline__ uint32_t smem_u32(const void* p) {
    uint32_t a;
    asm("{ .reg .u64 t; cvta.to.shared.u64 t, %1; cvt.u32.u64 %0, t; }" : "=r"(a) : "l"(p));
    return a;
}

// ---------------------------------------------------------------------------
// Kernel 0: convert weights to fp16 plane (content handled in proj_bg)
// ---------------------------------------------------------------------------
#define N4_W (1024 * 2048 / 4)

__global__ __launch_bounds__(256)
void cvt_w(const float4* __restrict__ kw, const float4* __restrict__ vw)
{
    int i = blockIdx.x * blockDim.x + threadIdx.x;
    const int total = 2 * N4_W;
    const int stride = gridDim.x * blockDim.x;
    for (; i < total; i += stride) {
        const float4* src = (i < N4_W) ? kw : vw;
        uint2* dst = (i < N4_W) ? (uint2*)g_Bf16 : (uint2*)(g_Bf16 + 1024 * 2048);
        int j = (i < N4_W) ? i : i - N4_W;
        float4 x = src[j];
        uint2 hv;
        asm("cvt.rn.f16x2.f32 %0, %2, %1;" : "=r"(hv.x) : "f"(x.x), "f"(x.y));
        asm("cvt.rn.f16x2.f32 %0, %2, %1;" : "=r"(hv.y) : "f"(x.z), "f"(x.w));
        dst[j] = hv;
    }
}

// ---------------------------------------------------------------------------
// Kernel 2 (runs first): beta/gamma logits + content->fp16 conversion fused.
// Block = 32 rows x 32 outputs, 2x2 register blocking.
// ---------------------------------------------------------------------------
__global__ __launch_bounds__(256)
void proj_bg(const float* __restrict__ A,
             const float* __restrict__ b_w,
             const float* __restrict__ ts_w,
             const float* __restrict__ b_b,
             const float* __restrict__ ts_b)
{
    __shared__ float As[32][128];
    __shared__ float Ws[32][129];

    const int rb = blockIdx.x * 32;
    const int tid = threadIdx.x;
    const int r0 = (tid >> 4) * 2;
    const int j0 = (tid & 15) * 2;
    float a00 = 0.f, a01 = 0.f, a10 = 0.f, a11 = 0.f;

    for (int k0 = 0; k0 < DD; k0 += 128) {
        __syncthreads();
        // stage A as float2, convert to fp16 on the way
#pragma unroll
        for (int it = 0; it < 8; it++) {
            int idx = tid + it * 256;          // 0..2047 float2
            int row = idx >> 6, c2 = idx & 63;
            const float2 v = *reinterpret_cast<const float2*>(
                A + (size_t)(rb + row) * DD + k0 + c2 * 2);
            As[row][c2 * 2] = v.x;
            As[row][c2 * 2 + 1] = v.y;
            uint32_t h;
            asm("cvt.rn.f16x2.f32 %0, %2, %1;" : "=r"(h) : "f"(v.x), "f"(v.y));
            *reinterpret_cast<uint32_t*>(
                g_Af16 + (size_t)(rb + row) * DD + k0 + c2 * 2) = h;
        }
        // stage W as float2
#pragma unroll
        for (int it = 0; it < 8; it++) {
            int idx = tid + it * 256;
            int wr = idx >> 6, wc2 = idx & 63;
            const float* wsrc = (wr < 16) ? (b_w + (size_t)wr * DD)
                                          : (ts_w + (size_t)(wr - 16) * DD);
            const float2 v = *reinterpret_cast<const float2*>(wsrc + k0 + wc2 * 2);
            Ws[wr][wc2 * 2] = v.x;
            Ws[wr][wc2 * 2 + 1] = v.y;
        }
        __syncthreads();
#pragma unroll 4
        for (int d = 0; d < 128; d++) {
            float x0 = As[r0][d], x1 = As[r0 + 1][d];
            float w0 = Ws[j0][d], w1 = Ws[j0 + 1][d];
            a00 = fmaf(x0, w0, a00);
            a01 = fmaf(x0, w1, a01);
            a10 = fmaf(x1, w0, a10);
            a11 = fmaf(x1, w1, a11);
        }
    }

    float bias0 = (j0 < 16) ? b_b[j0] : ts_b[j0 - 16];
    float bias1 = (j0 + 1 < 16) ? b_b[j0 + 1] : ts_b[j0 + 1 - 16];
    g_bg[(size_t)(rb + r0) * 32 + j0]         = a00 + bias0;
    g_bg[(size_t)(rb + r0) * 32 + j0 + 1]     = a01 + bias1;
    g_bg[(size_t)(rb + r0 + 1) * 32 + j0]     = a10 + bias0;
    g_bg[(size_t)(rb + r0 + 1) * 32 + j0 + 1] = a11 + bias1;
}

// ---------------------------------------------------------------------------
// Kernel 1: GEMM, single-product fp16.
// CTA 128x128, K-chunk 16, 4-stage cp.async pipeline, warp layout 2x4.
// ---------------------------------------------------------------------------
#define TM 128
#define TN 128
#define TK 16
#define NCH (DD / TK)        // 128
#define PITCH 48
#define PLANE (128 * PITCH)  // 6144
#define STAGE (2 * PLANE)    // 12288
#define NSTG 4
#define SMEMG (NSTG * STAGE) // 49152

__device__ __forceinline__ void ldmx4(uint32_t* r, uint32_t addr) {
    asm volatile("ldmatrix.sync.aligned.m8n8.x4.shared.b16 {%0,%1,%2,%3}, [%4];"
                 : "=r"(r[0]), "=r"(r[1]), "=r"(r[2]), "=r"(r[3]) : "r"(addr));
}
__device__ __forceinline__ void mma16816(float* d, const uint32_t* a,
                                         uint32_t b0, uint32_t b1) {
    asm volatile(
        "mma.sync.aligned.m16n8k16.row.col.f32.f16.f16.f32 "
        "{%0,%1,%2,%3}, {%4,%5,%6,%7}, {%8,%9}, {%0,%1,%2,%3};"
        : "+f"(d[0]), "+f"(d[1]), "+f"(d[2]), "+f"(d[3])
        : "r"(a[0]), "r"(a[1]), "r"(a[2]), "r"(a[3]), "r"(b0), "r"(b1));
}
__device__ __forceinline__ void cpasync16(uint32_t dst, const void* src) {
    asm volatile("cp.async.cg.shared.global [%0], [%1], 16;"
                 :: "r"(dst), "l"(src) : "memory");
}

__global__ __launch_bounds__(256, 2)
void gemm_kv_mma(void)
{
    extern __shared__ char sm[];
    const uint32_t sb = smem_u32(sm);
    const int tid = threadIdx.x;
    const int wid = tid >> 5;
    const int lane = tid & 31;
    const int wm = wid >> 2;
    const int wn = wid & 3;

    const int m0 = blockIdx.y * TM;
    const int n0 = blockIdx.x * TN;

    const int crow = tid >> 1;
    const int q = tid & 1;
    const __half* srcA = g_Af16 + (size_t)(m0 + crow) * DD + q * 8;
    const __half* srcB = g_Bf16 + (size_t)(n0 + crow) * DD + q * 8;
    const uint32_t dbase = (uint32_t)(crow * PITCH + q * 16);

    float acc[4][4][4];
#pragma unroll
    for (int i = 0; i < 4; i++)
#pragma unroll
        for (int j = 0; j < 4; j++)
#pragma unroll
            for (int qq = 0; qq < 4; qq++) acc[i][j][qq] = 0.f;

    const uint32_t a_off =
        (uint32_t)((wm * 64 + (lane & 15)) * PITCH + ((lane & 16) ? 16 : 0));
    const uint32_t b_off =
        (uint32_t)((wn * 32 + (lane & 7) + ((lane & 16) ? 8 : 0)) * PITCH +
                   ((lane & 8) ? 16 : 0));

#define ISSUE_CHUNK(c)                                                          \
    do {                                                                        \
        const int k0_ = (c) * TK;                                               \
        const uint32_t st_ = sb + ((c) & (NSTG - 1)) * STAGE;                   \
        cpasync16(st_ + dbase,         srcA + k0_);                             \
        cpasync16(st_ + PLANE + dbase, srcB + k0_);                             \
        asm volatile("cp.async.commit_group;" ::: "memory");                    \
    } while (0)

    ISSUE_CHUNK(0);
    ISSUE_CHUNK(1);
    ISSUE_CHUNK(2);

    for (int c = 0; c < NCH; c++) {
        asm volatile("cp.async.wait_group 2;" ::: "memory");
        __syncthreads();
        const uint32_t st = sb + (c & (NSTG - 1)) * STAGE;

        uint32_t Af[4][4];
#pragma unroll
        for (int mt = 0; mt < 4; mt++)
            ldmx4(Af[mt], st + a_off + mt * 16 * PITCH);
#pragma unroll
        for (int np = 0; np < 2; np++) {
            uint32_t Bf[4];
            ldmx4(Bf, st + PLANE + b_off + np * 16 * PITCH);
#pragma unroll
            for (int mt = 0; mt < 4; mt++) {
                mma16816(acc[mt][2 * np],     Af[mt], Bf[0], Bf[1]);
                mma16816(acc[mt][2 * np + 1], Af[mt], Bf[2], Bf[3]);
            }
        }

        if (c + 3 < NCH) {
            ISSUE_CHUNK(c + 3);
        } else {
            asm volatile("cp.async.commit_group;" ::: "memory");
        }
    }

#pragma unroll
    for (int mt = 0; mt < 4; mt++) {
        const int row = m0 + wm * 64 + mt * 16 + (lane >> 2);
#pragma unroll
        for (int nt = 0; nt < 4; nt++) {
            const int col = n0 + wn * 32 + nt * 8 + 2 * (lane & 3);
            float* p0 = g_proj + (size_t)row * DD + col;
            float* p1 = g_proj + (size_t)(row + 8) * DD + col;
            *reinterpret_cast<float2*>(p0) = make_float2(acc[mt][nt][0], acc[mt][nt][1]);
            *reinterpret_cast<float2*>(p1) = make_float2(acc[mt][nt][2], acc[mt][nt][3]);
        }
    }
}

// ---------------------------------------------------------------------------
// Kernel 3: recurrence, gamma factored (W = S*U), renorm every 16 steps.
// Precomputed beta/gamma for all 256 steps; ninv folded into scalars.
// 128 threads, lane pairs split DK (32 cols each).
// ---------------------------------------------------------------------------
#define CH 32
#define KROW 72

__global__ __launch_bounds__(128)
void recurrent_update(const float* __restrict__ W_old,
                      const float* __restrict__ hd,
                      float* __restrict__ out)
{
    const int bh = blockIdx.x;
    const int b = bh >> 4;
    const int h = bh & 15;
    const int tid = threadIdx.x;
    const int v = tid >> 1;
    const int half = tid & 1;
    const int cb = half ? 36 : 0;

    __shared__ float ks[CH][KROW];
    __shared__ float vs[CH][DKK];
    __shared__ float betas[TT], gams[TT], ginvs[TT];
    __shared__ float ninv[CH];

    float U[32];
    const float* wrow = W_old + ((size_t)bh * DKK + v) * DKK + half * 32;
#pragma unroll
    for (int d = 0; d < 32; d += 4) {
        float4 t = *reinterpret_cast<const float4*>(&wrow[d]);
        U[d] = t.x; U[d+1] = t.y; U[d+2] = t.z; U[d+3] = t.w;
    }
    const float hdl = hd[h];

    // precompute per-step scalars with all 128 threads (2 steps each)
    for (int i = tid; i < TT; i += 128) {
        size_t brow = (size_t)(b * TT + i) * 32;
        betas[i] = 1.f / (1.f + expf(-g_bg[brow + h]));
        float gm = 1.f / (1.f + expf(-(g_bg[brow + 16 + h] + hdl)));
        gams[i] = gm;
        ginvs[i] = 1.f / gm;
    }

    for (int t0 = 0; t0 < TT; t0 += CH) {
        __syncthreads();
        for (int i = tid; i < CH * DKK; i += 128) {
            int s = i >> 6, d = i & 63;
            int col = d + ((d >= 32) ? 4 : 0);
            size_t row = (size_t)(b * TT + t0 + s) * DD;
            ks[s][col] = g_proj[row + h * DKK + d];
            vs[s][d] = g_proj[row + 1024 + h * DKK + d];
        }
        __syncthreads();
        // ninv: 4 lanes per step, 16 elems each, shfl-quad reduce
        {
            int s = tid >> 2, qq = tid & 3;
            int base = qq * 16 + ((qq >= 2) ? 4 : 0);
            float nsq = 0.f;
#pragma unroll
            for (int d = 0; d < 16; d++) {
                float x = ks[s][base + d];
                nsq = fmaf(x, x, nsq);
            }
            nsq += __shfl_xor_sync(0xffffffffu, nsq, 1);
            nsq += __shfl_xor_sync(0xffffffffu, nsq, 2);
            if (qq == 0) ninv[s] = rsqrtf(fmaxf(nsq, 1e-24f));
        }
        __syncthreads();

#pragma unroll
        for (int hcb = 0; hcb < CH; hcb += 16) {
            float S = 1.f, invS = 1.f;
            for (int s = hcb; s < hcb + 16; s++) {
                const int t = t0 + s;
                S *= gams[t];
                invS *= ginvs[t];
                float kr[32];
#pragma unroll
                for (int d = 0; d < 32; d += 4) {
                    float4 tv = *reinterpret_cast<const float4*>(&ks[s][cb + d]);
                    kr[d] = tv.x; kr[d+1] = tv.y; kr[d+2] = tv.z; kr[d+3] = tv.w;
                }
                float a0 = 0.f, a1 = 0.f, a2 = 0.f, a3 = 0.f;
#pragma unroll
                for (int d = 0; d < 32; d += 4) {
                    a0 = fmaf(U[d],     kr[d],     a0);
                    a1 = fmaf(U[d + 1], kr[d + 1], a1);
                    a2 = fmaf(U[d + 2], kr[d + 2], a2);
                    a3 = fmaf(U[d + 3], kr[d + 3], a3);
                }
                float yr = (a0 + a1) + (a2 + a3);
                yr += __shfl_xor_sync(0xffffffffu, yr, 1);
                const float nv = ninv[s];
                float y = yr * nv;                        // U·k̂ (raw dot normalized)
                float yprev = S * ginvs[t] * y;           // S_{t-1} * (U·k̂)
                float cc = betas[t] * (vs[s][v] - yprev) * invS * nv;
#pragma unroll
                for (int d = 0; d < 32; d++)
                    U[d] = fmaf(cc, kr[d], U[d]);
            }
#pragma unroll
            for (int d = 0; d < 32; d++)
                U[d] *= S;
        }
    }

    float* orow = out + ((size_t)bh * DKK + v) * DKK + half * 32;
#pragma unroll
    for (int d = 0; d < 32; d += 4) {
        float4 t = make_float4(U[d], U[d+1], U[d+2], U[d+3]);
        *reinterpret_cast<float4*>(&orow[d]) = t;
    }
}

// ---------------------------------------------------------------------------
extern "C" void kernel_launch(void* const* d_in, const int* in_sizes, int n_in,
                              void* d_out, int out_size)
{
    const float* W_old   = (const float*)d_in[0];
    const float* content = (const float*)d_in[1];
    const float* k_w     = (const float*)d_in[2];
    const float* v_w     = (const float*)d_in[3];
    const float* b_w     = (const float*)d_in[4];
    const float* b_b     = (const float*)d_in[5];
    const float* ts_w    = (const float*)d_in[6];
    const float* ts_b    = (const float*)d_in[7];
    const float* hd      = (const float*)d_in[8];
    float* out = (float*)d_out;

    cvt_w<<<1024, 256>>>((const float4*)k_w, (const float4*)v_w);
    proj_bg<<<256, 256>>>(content, b_w, ts_w, b_b, ts_b);   // also emits g_Af16

    cudaFuncSetAttribute(gemm_kv_mma, cudaFuncAttributeMaxDynamicSharedMemorySize,
                         SMEMG);
    dim3 g1(DD / TN, 8192 / TM);   // (16, 64)
    gemm_kv_mma<<<g1, 256, SMEMG>>>();
    recurrent_update<<<BB * HH, 128>>>(W_old, hd, out);
}